// round 1
// baseline (speedup 1.0000x reference)
#include <cuda_runtime.h>
#include <math.h>

// Problem constants
#define BB 4
#define SS 1024
#define DD 1024
#define HH 16
#define DH 64
#define MR (BB * SS)   // 4096 rows

// ---------------- scratch (static device globals; allocation-free) ----------
__device__ float g_qp[MR * DD];
__device__ float g_kp[MR * DD];
__device__ float g_vp[MR * DD];
__device__ float g_attn[MR * DD];
__device__ float g_bias[BB * SS];

// ---------------- mask -> additive bias, with dtype autodetect --------------
// mask/semask are (B,1,1,S) boolean in the reference; serialized dtype unknown.
// Detect: bool8 (1B, 0/1), int32 (nonzero only at byte%4==0), float32 (0x80/0x3f
// bytes at off positions).
__global__ void __launch_bounds__(256) mask_bias_kernel(
    const unsigned char* __restrict__ m8, const unsigned char* __restrict__ s8)
{
    __shared__ int flag_off, flag_f32;
    if (threadIdx.x == 0) { flag_off = 0; flag_f32 = 0; }
    __syncthreads();

    int loc_off = 0, loc_f32 = 0;
    for (int p = threadIdx.x; p < BB * SS; p += blockDim.x) {
        unsigned char bm = m8[p];
        unsigned char bs = s8[p];
        if ((p & 3) != 0) {
            if (bm | bs) loc_off = 1;
            if (bm == 0x3f || bm == 0x80 || bs == 0x3f || bs == 0x80) loc_f32 = 1;
        }
    }
    if (loc_off) atomicOr(&flag_off, 1);
    if (loc_f32) atomicOr(&flag_f32, 1);
    __syncthreads();

    int code = flag_f32 ? 2 : (flag_off ? 0 : 1);  // 0=bool8, 1=int32, 2=f32

    for (int i = threadIdx.x; i < BB * SS; i += blockDim.x) {
        bool mv, sv;
        if (code == 0) {
            mv = m8[i] != 0;
            sv = s8[i] != 0;
        } else if (code == 1) {
            mv = ((const int*)m8)[i] != 0;
            sv = ((const int*)s8)[i] != 0;
        } else {
            mv = ((const float*)m8)[i] != 0.0f;
            sv = ((const float*)s8)[i] != 0.0f;
        }
        g_bias[i] = (mv || sv) ? -1e9f : 0.0f;
    }
}

// ---------------- SGEMM: C[M,N] = A[M,K] * W[N,K]^T + bias[N] ---------------
// M=4096, N=K=1024 fixed. 128x128 block tile, K-step 16, 8x8 per-thread tile.
__global__ void __launch_bounds__(256) gemm_nt(
    const float* __restrict__ A, const float* __restrict__ W,
    const float* __restrict__ bias, float* __restrict__ C)
{
    const int K = 1024, N = 1024;
    __shared__ float As[16][128];
    __shared__ float Ws[16][128];

    int tid = threadIdx.x;
    int bn = blockIdx.x * 128;
    int bm = blockIdx.y * 128;
    int ty = tid >> 4, tx = tid & 15;

    float acc[8][8];
#pragma unroll
    for (int i = 0; i < 8; i++)
#pragma unroll
        for (int j = 0; j < 8; j++) acc[i][j] = 0.0f;

    for (int k0 = 0; k0 < K; k0 += 16) {
#pragma unroll
        for (int l = 0; l < 2; l++) {
            int s   = tid * 2 + l;
            int row = s >> 2;
            int c4  = (s & 3) * 4;
            float4 a4 = *(const float4*)&A[(size_t)(bm + row) * K + k0 + c4];
            As[c4 + 0][row] = a4.x;
            As[c4 + 1][row] = a4.y;
            As[c4 + 2][row] = a4.z;
            As[c4 + 3][row] = a4.w;
            float4 w4 = *(const float4*)&W[(size_t)(bn + row) * K + k0 + c4];
            Ws[c4 + 0][row] = w4.x;
            Ws[c4 + 1][row] = w4.y;
            Ws[c4 + 2][row] = w4.z;
            Ws[c4 + 3][row] = w4.w;
        }
        __syncthreads();
#pragma unroll
        for (int kk = 0; kk < 16; kk++) {
            float ra[8], rb[8];
            *(float4*)&ra[0] = *(const float4*)&As[kk][ty * 8];
            *(float4*)&ra[4] = *(const float4*)&As[kk][ty * 8 + 4];
            *(float4*)&rb[0] = *(const float4*)&Ws[kk][tx * 8];
            *(float4*)&rb[4] = *(const float4*)&Ws[kk][tx * 8 + 4];
#pragma unroll
            for (int i = 0; i < 8; i++)
#pragma unroll
                for (int j = 0; j < 8; j++) acc[i][j] += ra[i] * rb[j];
        }
        __syncthreads();
    }

#pragma unroll
    for (int i = 0; i < 8; i++) {
        size_t row = bm + ty * 8 + i;
#pragma unroll
        for (int j = 0; j < 8; j += 4) {
            int col = bn + tx * 8 + j;
            float4 r;
            r.x = acc[i][j + 0] + bias[col + 0];
            r.y = acc[i][j + 1] + bias[col + 1];
            r.z = acc[i][j + 2] + bias[col + 2];
            r.w = acc[i][j + 3] + bias[col + 3];
            *(float4*)&C[row * N + col] = r;
        }
    }
}

// ---------------- flash attention -------------------------------------------
// grid: (B*H, S/64). block 256 = 16x16 threads; thread (ty,tx) owns query rows
// 4ty..4ty+3 and (score phase) keys 4tx..4tx+3 / (output) dims 4tx..4tx+3.
// smem 48KB exactly: sQ[64x64] + sKV[64x64] (K^T then V) + sP[64x64].
__global__ void __launch_bounds__(256) attn_kernel()
{
    __shared__ float sQ[64 * 64];
    __shared__ float sKV[64 * 64];
    __shared__ float sP[64 * 64];

    int tid = threadIdx.x;
    int bh  = blockIdx.x;
    int b   = bh >> 4;
    int h   = bh & 15;
    int q0  = blockIdx.y * 64;
    int ty  = tid >> 4, tx = tid & 15;

    // load Q tile [64 rows][64 dims]
    {
        int row = tid >> 2;
        int c0  = (tid & 3) * 16;
        const float4* src =
            (const float4*)(g_qp + (size_t)(b * SS + q0 + row) * DD + h * DH + c0);
        float4* dst = (float4*)&sQ[row * 64 + c0];
        dst[0] = src[0]; dst[1] = src[1]; dst[2] = src[2]; dst[3] = src[3];
    }

    float o[4][4];
    float mrow[4], lrow[4];
#pragma unroll
    for (int i = 0; i < 4; i++) {
        mrow[i] = -INFINITY;
        lrow[i] = 0.0f;
#pragma unroll
        for (int j = 0; j < 4; j++) o[i][j] = 0.0f;
    }

    for (int kt = 0; kt < SS / 64; kt++) {
        int k0 = kt * 64;
        __syncthreads();  // previous PV done with sKV/sP (and Q visible on iter 0 via next sync)
        // load K transposed: sKV[d*64 + krow] = K[k0+krow][d]
        {
            int row = tid >> 2;
            int c0  = (tid & 3) * 16;
            const float4* src =
                (const float4*)(g_kp + (size_t)(b * SS + k0 + row) * DD + h * DH + c0);
#pragma unroll
            for (int u = 0; u < 4; u++) {
                float4 v4 = src[u];
                int d = c0 + u * 4;
                sKV[(d + 0) * 64 + row] = v4.x;
                sKV[(d + 1) * 64 + row] = v4.y;
                sKV[(d + 2) * 64 + row] = v4.z;
                sKV[(d + 3) * 64 + row] = v4.w;
            }
        }
        __syncthreads();

        // scores S = Q K^T
        float s[4][4];
#pragma unroll
        for (int i = 0; i < 4; i++)
#pragma unroll
            for (int j = 0; j < 4; j++) s[i][j] = 0.0f;

#pragma unroll 8
        for (int d = 0; d < 64; d++) {
            float4 k4 = *(const float4*)&sKV[d * 64 + tx * 4];
            float qv[4];
#pragma unroll
            for (int i = 0; i < 4; i++) qv[i] = sQ[(ty * 4 + i) * 64 + d];
#pragma unroll
            for (int i = 0; i < 4; i++) {
                s[i][0] += qv[i] * k4.x;
                s[i][1] += qv[i] * k4.y;
                s[i][2] += qv[i] * k4.z;
                s[i][3] += qv[i] * k4.w;
            }
        }

        float bias4[4];
#pragma unroll
        for (int j = 0; j < 4; j++) bias4[j] = g_bias[b * SS + k0 + tx * 4 + j];

        // online softmax update per owned row
#pragma unroll
        for (int i = 0; i < 4; i++) {
            float mx = -INFINITY;
#pragma unroll
            for (int j = 0; j < 4; j++) {
                s[i][j] = s[i][j] * 0.125f + bias4[j];
                mx = fmaxf(mx, s[i][j]);
            }
#pragma unroll
            for (int off = 8; off > 0; off >>= 1)
                mx = fmaxf(mx, __shfl_xor_sync(0xffffffffu, mx, off));
            float mn   = fmaxf(mrow[i], mx);
            float corr = __expf(mrow[i] - mn);
            mrow[i]    = mn;
            float ls = 0.0f;
#pragma unroll
            for (int j = 0; j < 4; j++) {
                float p = __expf(s[i][j] - mn);
                s[i][j] = p;
                ls += p;
            }
#pragma unroll
            for (int off = 8; off > 0; off >>= 1)
                ls += __shfl_xor_sync(0xffffffffu, ls, off);
            lrow[i] = lrow[i] * corr + ls;
#pragma unroll
            for (int j = 0; j < 4; j++) o[i][j] *= corr;
            // store probabilities
            float4 p4;
            p4.x = s[i][0]; p4.y = s[i][1]; p4.z = s[i][2]; p4.w = s[i][3];
            *(float4*)&sP[(ty * 4 + i) * 64 + tx * 4] = p4;
        }

        __syncthreads();
        // load V (natural layout) into sKV
        {
            int row = tid >> 2;
            int c0  = (tid & 3) * 16;
            const float4* src =
                (const float4*)(g_vp + (size_t)(b * SS + k0 + row) * DD + h * DH + c0);
            float4* dst = (float4*)&sKV[row * 64 + c0];
            dst[0] = src[0]; dst[1] = src[1]; dst[2] = src[2]; dst[3] = src[3];
        }
        __syncthreads();

        // O += P V
#pragma unroll 8
        for (int k = 0; k < 64; k++) {
            float4 v4 = *(const float4*)&sKV[k * 64 + tx * 4];
            float pv[4];
#pragma unroll
            for (int i = 0; i < 4; i++) pv[i] = sP[(ty * 4 + i) * 64 + k];
#pragma unroll
            for (int i = 0; i < 4; i++) {
                o[i][0] += pv[i] * v4.x;
                o[i][1] += pv[i] * v4.y;
                o[i][2] += pv[i] * v4.z;
                o[i][3] += pv[i] * v4.w;
            }
        }
    }

    // normalize + write merged-heads layout [B,S,D]
#pragma unroll
    for (int i = 0; i < 4; i++) {
        float inv = 1.0f / lrow[i];
        float4 r;
        r.x = o[i][0] * inv;
        r.y = o[i][1] * inv;
        r.z = o[i][2] * inv;
        r.w = o[i][3] * inv;
        *(float4*)&g_attn[(size_t)(b * SS + q0 + ty * 4 + i) * DD + h * DH + tx * 4] = r;
    }
}

// ---------------- launch -----------------------------------------------------
extern "C" void kernel_launch(void* const* d_in, const int* in_sizes, int n_in,
                              void* d_out, int out_size)
{
    const float* v  = (const float*)d_in[0];
    const float* k  = (const float*)d_in[1];
    const float* q  = (const float*)d_in[2];
    const unsigned char* mask   = (const unsigned char*)d_in[3];
    const unsigned char* semask = (const unsigned char*)d_in[4];
    const float* Wv = (const float*)d_in[5];
    const float* bv = (const float*)d_in[6];
    const float* Wk = (const float*)d_in[7];
    const float* bk = (const float*)d_in[8];
    const float* Wq = (const float*)d_in[9];
    const float* bq = (const float*)d_in[10];
    const float* Wm = (const float*)d_in[11];
    const float* bm = (const float*)d_in[12];
    float* out = (float*)d_out;

    float *pq, *pk, *pv, *pa;
    cudaGetSymbolAddress((void**)&pq, g_qp);
    cudaGetSymbolAddress((void**)&pk, g_kp);
    cudaGetSymbolAddress((void**)&pv, g_vp);
    cudaGetSymbolAddress((void**)&pa, g_attn);

    mask_bias_kernel<<<1, 256>>>(mask, semask);

    dim3 gg(1024 / 128, MR / 128);  // (8, 32)
    gemm_nt<<<gg, 256>>>(v, Wv, bv, pv);
    gemm_nt<<<gg, 256>>>(k, Wk, bk, pk);
    gemm_nt<<<gg, 256>>>(q, Wq, bq, pq);

    attn_kernel<<<dim3(BB * HH, SS / 64), 256>>>();

    gemm_nt<<<gg, 256>>>(pa, Wm, bm, out);
}

// round 2
// speedup vs baseline: 1.6106x; 1.6106x over previous
#include <cuda_runtime.h>
#include <math.h>
#include <stdint.h>

// Problem constants
#define BB 4
#define SS 1024
#define DD 1024
#define HH 16
#define DH 64
#define MR (BB * SS)   // 4096 rows

// ---------------- scratch (static device globals; allocation-free) ----------
__device__ float g_qp[MR * DD];
__device__ float g_kp[MR * DD];
__device__ float g_vp[MR * DD];
__device__ float g_attn[MR * DD];
__device__ float g_bias[BB * SS];

// ---------------- small PTX helpers -----------------------------------------
__device__ __forceinline__ uint32_t f2tf(float x) {
    uint32_t r;
    asm("cvt.rna.tf32.f32 %0, %1;" : "=r"(r) : "f"(x));
    return r;
}

__device__ __forceinline__ void mma_tf32(float c[4],
                                         uint32_t a0, uint32_t a1, uint32_t a2, uint32_t a3,
                                         uint32_t b0, uint32_t b1) {
    asm volatile(
        "mma.sync.aligned.m16n8k8.row.col.f32.tf32.tf32.f32 "
        "{%0,%1,%2,%3}, {%4,%5,%6,%7}, {%8,%9}, {%0,%1,%2,%3};"
        : "+f"(c[0]), "+f"(c[1]), "+f"(c[2]), "+f"(c[3])
        : "r"(a0), "r"(a1), "r"(a2), "r"(a3), "r"(b0), "r"(b1));
}

__device__ __forceinline__ void cp_async16(void* smem, const void* gmem) {
    uint32_t s = (uint32_t)__cvta_generic_to_shared(smem);
    asm volatile("cp.async.cg.shared.global [%0], [%1], 16;" :: "r"(s), "l"(gmem));
}
#define CP_COMMIT asm volatile("cp.async.commit_group;")
#define CP_WAIT0  asm volatile("cp.async.wait_group 0;")

// ---------------- mask -> additive bias, with dtype autodetect --------------
__global__ void __launch_bounds__(256) mask_bias_kernel(
    const unsigned char* __restrict__ m8, const unsigned char* __restrict__ s8)
{
    __shared__ int flag_off, flag_f32;
    if (threadIdx.x == 0) { flag_off = 0; flag_f32 = 0; }
    __syncthreads();

    int loc_off = 0, loc_f32 = 0;
    for (int p = threadIdx.x; p < BB * SS; p += blockDim.x) {
        unsigned char bm = m8[p];
        unsigned char bs = s8[p];
        if ((p & 3) != 0) {
            if (bm | bs) loc_off = 1;
            if (bm == 0x3f || bm == 0x80 || bs == 0x3f || bs == 0x80) loc_f32 = 1;
        }
    }
    if (loc_off) atomicOr(&flag_off, 1);
    if (loc_f32) atomicOr(&flag_f32, 1);
    __syncthreads();

    int code = flag_f32 ? 2 : (flag_off ? 0 : 1);  // 0=bool8, 1=int32, 2=f32

    for (int i = threadIdx.x; i < BB * SS; i += blockDim.x) {
        bool mv, sv;
        if (code == 0) {
            mv = m8[i] != 0;
            sv = s8[i] != 0;
        } else if (code == 1) {
            mv = ((const int*)m8)[i] != 0;
            sv = ((const int*)s8)[i] != 0;
        } else {
            mv = ((const float*)m8)[i] != 0.0f;
            sv = ((const float*)s8)[i] != 0.0f;
        }
        g_bias[i] = (mv || sv) ? -1e9f : 0.0f;
    }
}

// ---------------- tf32 tensor-core GEMM: C = A[M,K] * W[N,K]^T + bias[N] ----
// M=4096, N=K=1024. 128x128 block tile, BK=16 double-buffered via cp.async.
// 8 warps in 4x2 grid; warp tile 32x64 = 2(m16) x 8(n8) mma tiles.
#define BM 128
#define BN 128
#define BKG 16
#define SPAD 20   // smem row stride (floats): 80B, 16B-aligned, conflict-free

__global__ void __launch_bounds__(256) gemm_tf32(
    const float* __restrict__ A, const float* __restrict__ W,
    const float* __restrict__ bias, float* __restrict__ C)
{
    const int K = 1024, N = 1024;
    __shared__ float As[2][BM * SPAD];
    __shared__ float Ws[2][BN * SPAD];

    int tid  = threadIdx.x;
    int bn   = blockIdx.x * BN;
    int bm   = blockIdx.y * BM;
    int warp = tid >> 5, lane = tid & 31;
    int r = lane >> 2, g = lane & 3;
    int wm = (warp >> 1) * 32;   // warp row offset within tile
    int wn = (warp & 1) * 64;    // warp col offset within tile

    float acc[2][8][4];
#pragma unroll
    for (int mi = 0; mi < 2; mi++)
#pragma unroll
        for (int ni = 0; ni < 8; ni++)
#pragma unroll
            for (int e = 0; e < 4; e++) acc[mi][ni][e] = 0.0f;

    // --- prologue: stage 0 ---
    {
#pragma unroll
        for (int u = 0; u < 2; u++) {
            int ch  = tid + u * 256;      // 0..511
            int row = ch >> 2;            // 128 rows, 4 chunks per row
            int kc  = (ch & 3) * 4;
            cp_async16(&As[0][row * SPAD + kc], &A[(size_t)(bm + row) * K + kc]);
            cp_async16(&Ws[0][row * SPAD + kc], &W[(size_t)(bn + row) * K + kc]);
        }
        CP_COMMIT;
    }

    int buf = 0;
    for (int k0 = 0; k0 < K; k0 += BKG) {
        CP_WAIT0;
        __syncthreads();

        if (k0 + BKG < K) {
            int nb = buf ^ 1;
            int kn = k0 + BKG;
#pragma unroll
            for (int u = 0; u < 2; u++) {
                int ch  = tid + u * 256;
                int row = ch >> 2;
                int kc  = (ch & 3) * 4;
                cp_async16(&As[nb][row * SPAD + kc], &A[(size_t)(bm + row) * K + kn + kc]);
                cp_async16(&Ws[nb][row * SPAD + kc], &W[(size_t)(bn + row) * K + kn + kc]);
            }
            CP_COMMIT;
        }

        const float* as = As[buf];
        const float* ws = Ws[buf];
#pragma unroll
        for (int kk = 0; kk < BKG; kk += 8) {
            uint32_t a[2][4];
#pragma unroll
            for (int mi = 0; mi < 2; mi++) {
                int base = (wm + mi * 16 + r) * SPAD + kk + g;
                a[mi][0] = f2tf(as[base]);
                a[mi][1] = f2tf(as[base + 8 * SPAD]);
                a[mi][2] = f2tf(as[base + 4]);
                a[mi][3] = f2tf(as[base + 8 * SPAD + 4]);
            }
            uint32_t b[8][2];
#pragma unroll
            for (int ni = 0; ni < 8; ni++) {
                int base = (wn + ni * 8 + r) * SPAD + kk + g;
                b[ni][0] = f2tf(ws[base]);
                b[ni][1] = f2tf(ws[base + 4]);
            }
#pragma unroll
            for (int mi = 0; mi < 2; mi++)
#pragma unroll
                for (int ni = 0; ni < 8; ni++)
                    mma_tf32(acc[mi][ni], a[mi][0], a[mi][1], a[mi][2], a[mi][3],
                             b[ni][0], b[ni][1]);
        }
        buf ^= 1;
    }

    // --- epilogue: bias + store ---
#pragma unroll
    for (int mi = 0; mi < 2; mi++) {
        int row0 = bm + wm + mi * 16 + r;
#pragma unroll
        for (int ni = 0; ni < 8; ni++) {
            int col = bn + wn + ni * 8 + 2 * g;
            float b0 = bias[col], b1 = bias[col + 1];
            float2 v0, v1;
            v0.x = acc[mi][ni][0] + b0;
            v0.y = acc[mi][ni][1] + b1;
            v1.x = acc[mi][ni][2] + b0;
            v1.y = acc[mi][ni][3] + b1;
            *(float2*)&C[(size_t)row0 * N + col]       = v0;
            *(float2*)&C[(size_t)(row0 + 8) * N + col] = v1;
        }
    }
}

// ---------------- flash attention (unchanged from R1) ------------------------
__global__ void __launch_bounds__(256) attn_kernel()
{
    __shared__ float sQ[64 * 64];
    __shared__ float sKV[64 * 64];
    __shared__ float sP[64 * 64];

    int tid = threadIdx.x;
    int bh  = blockIdx.x;
    int b   = bh >> 4;
    int h   = bh & 15;
    int q0  = blockIdx.y * 64;
    int ty  = tid >> 4, tx = tid & 15;

    {
        int row = tid >> 2;
        int c0  = (tid & 3) * 16;
        const float4* src =
            (const float4*)(g_qp + (size_t)(b * SS + q0 + row) * DD + h * DH + c0);
        float4* dst = (float4*)&sQ[row * 64 + c0];
        dst[0] = src[0]; dst[1] = src[1]; dst[2] = src[2]; dst[3] = src[3];
    }

    float o[4][4];
    float mrow[4], lrow[4];
#pragma unroll
    for (int i = 0; i < 4; i++) {
        mrow[i] = -INFINITY;
        lrow[i] = 0.0f;
#pragma unroll
        for (int j = 0; j < 4; j++) o[i][j] = 0.0f;
    }

    for (int kt = 0; kt < SS / 64; kt++) {
        int k0 = kt * 64;
        __syncthreads();
        {
            int row = tid >> 2;
            int c0  = (tid & 3) * 16;
            const float4* src =
                (const float4*)(g_kp + (size_t)(b * SS + k0 + row) * DD + h * DH + c0);
#pragma unroll
            for (int u = 0; u < 4; u++) {
                float4 v4 = src[u];
                int d = c0 + u * 4;
                sKV[(d + 0) * 64 + row] = v4.x;
                sKV[(d + 1) * 64 + row] = v4.y;
                sKV[(d + 2) * 64 + row] = v4.z;
                sKV[(d + 3) * 64 + row] = v4.w;
            }
        }
        __syncthreads();

        float s[4][4];
#pragma unroll
        for (int i = 0; i < 4; i++)
#pragma unroll
            for (int j = 0; j < 4; j++) s[i][j] = 0.0f;

#pragma unroll 8
        for (int d = 0; d < 64; d++) {
            float4 k4 = *(const float4*)&sKV[d * 64 + tx * 4];
            float qv[4];
#pragma unroll
            for (int i = 0; i < 4; i++) qv[i] = sQ[(ty * 4 + i) * 64 + d];
#pragma unroll
            for (int i = 0; i < 4; i++) {
                s[i][0] += qv[i] * k4.x;
                s[i][1] += qv[i] * k4.y;
                s[i][2] += qv[i] * k4.z;
                s[i][3] += qv[i] * k4.w;
            }
        }

        float bias4[4];
#pragma unroll
        for (int j = 0; j < 4; j++) bias4[j] = g_bias[b * SS + k0 + tx * 4 + j];

#pragma unroll
        for (int i = 0; i < 4; i++) {
            float mx = -INFINITY;
#pragma unroll
            for (int j = 0; j < 4; j++) {
                s[i][j] = s[i][j] * 0.125f + bias4[j];
                mx = fmaxf(mx, s[i][j]);
            }
#pragma unroll
            for (int off = 8; off > 0; off >>= 1)
                mx = fmaxf(mx, __shfl_xor_sync(0xffffffffu, mx, off));
            float mn   = fmaxf(mrow[i], mx);
            float corr = __expf(mrow[i] - mn);
            mrow[i]    = mn;
            float ls = 0.0f;
#pragma unroll
            for (int j = 0; j < 4; j++) {
                float p = __expf(s[i][j] - mn);
                s[i][j] = p;
                ls += p;
            }
#pragma unroll
            for (int off = 8; off > 0; off >>= 1)
                ls += __shfl_xor_sync(0xffffffffu, ls, off);
            lrow[i] = lrow[i] * corr + ls;
#pragma unroll
            for (int j = 0; j < 4; j++) o[i][j] *= corr;
            float4 p4;
            p4.x = s[i][0]; p4.y = s[i][1]; p4.z = s[i][2]; p4.w = s[i][3];
            *(float4*)&sP[(ty * 4 + i) * 64 + tx * 4] = p4;
        }

        __syncthreads();
        {
            int row = tid >> 2;
            int c0  = (tid & 3) * 16;
            const float4* src =
                (const float4*)(g_vp + (size_t)(b * SS + k0 + row) * DD + h * DH + c0);
            float4* dst = (float4*)&sKV[row * 64 + c0];
            dst[0] = src[0]; dst[1] = src[1]; dst[2] = src[2]; dst[3] = src[3];
        }
        __syncthreads();

#pragma unroll 8
        for (int k = 0; k < 64; k++) {
            float4 v4 = *(const float4*)&sKV[k * 64 + tx * 4];
            float pv[4];
#pragma unroll
            for (int i = 0; i < 4; i++) pv[i] = sP[(ty * 4 + i) * 64 + k];
#pragma unroll
            for (int i = 0; i < 4; i++) {
                o[i][0] += pv[i] * v4.x;
                o[i][1] += pv[i] * v4.y;
                o[i][2] += pv[i] * v4.z;
                o[i][3] += pv[i] * v4.w;
            }
        }
    }

#pragma unroll
    for (int i = 0; i < 4; i++) {
        float inv = 1.0f / lrow[i];
        float4 r;
        r.x = o[i][0] * inv;
        r.y = o[i][1] * inv;
        r.z = o[i][2] * inv;
        r.w = o[i][3] * inv;
        *(float4*)&g_attn[(size_t)(b * SS + q0 + ty * 4 + i) * DD + h * DH + tx * 4] = r;
    }
}

// ---------------- launch -----------------------------------------------------
extern "C" void kernel_launch(void* const* d_in, const int* in_sizes, int n_in,
                              void* d_out, int out_size)
{
    const float* v  = (const float*)d_in[0];
    const float* k  = (const float*)d_in[1];
    const float* q  = (const float*)d_in[2];
    const unsigned char* mask   = (const unsigned char*)d_in[3];
    const unsigned char* semask = (const unsigned char*)d_in[4];
    const float* Wv = (const float*)d_in[5];
    const float* bv = (const float*)d_in[6];
    const float* Wk = (const float*)d_in[7];
    const float* bk = (const float*)d_in[8];
    const float* Wq = (const float*)d_in[9];
    const float* bq = (const float*)d_in[10];
    const float* Wm = (const float*)d_in[11];
    const float* bm = (const float*)d_in[12];
    float* out = (float*)d_out;

    float *pq, *pk, *pv, *pa;
    cudaGetSymbolAddress((void**)&pq, g_qp);
    cudaGetSymbolAddress((void**)&pk, g_kp);
    cudaGetSymbolAddress((void**)&pv, g_vp);
    cudaGetSymbolAddress((void**)&pa, g_attn);

    mask_bias_kernel<<<1, 256>>>(mask, semask);

    dim3 gg(1024 / BN, MR / BM);  // (8, 32)
    gemm_tf32<<<gg, 256>>>(v, Wv, bv, pv);
    gemm_tf32<<<gg, 256>>>(k, Wk, bk, pk);
    gemm_tf32<<<gg, 256>>>(q, Wq, bq, pq);

    attn_kernel<<<dim3(BB * HH, SS / 64), 256>>>();

    gemm_tf32<<<gg, 256>>>(pa, Wm, bm, out);
}

// round 5
// speedup vs baseline: 2.6103x; 1.6207x over previous
#include <cuda_runtime.h>
#include <math.h>
#include <stdint.h>

// Problem constants
#define BB 4
#define SS 1024
#define DD 1024
#define HH 16
#define DH 64
#define MR (BB * SS)   // 4096 rows

// ---------------- scratch (static device globals; allocation-free) ----------
__device__ float g_qp[MR * DD];
__device__ float g_kp[MR * DD];
__device__ float g_vp[MR * DD];
__device__ float g_attn[MR * DD];
__device__ float g_bias[BB * SS];

// ---------------- small PTX helpers -----------------------------------------
__device__ __forceinline__ uint32_t f2tf(float x) {
    uint32_t r;
    asm("cvt.rna.tf32.f32 %0, %1;" : "=r"(r) : "f"(x));
    return r;
}

__device__ __forceinline__ void mma_tf32(float c[4],
                                         uint32_t a0, uint32_t a1, uint32_t a2, uint32_t a3,
                                         uint32_t b0, uint32_t b1) {
    asm volatile(
        "mma.sync.aligned.m16n8k8.row.col.f32.tf32.tf32.f32 "
        "{%0,%1,%2,%3}, {%4,%5,%6,%7}, {%8,%9}, {%0,%1,%2,%3};"
        : "+f"(c[0]), "+f"(c[1]), "+f"(c[2]), "+f"(c[3])
        : "r"(a0), "r"(a1), "r"(a2), "r"(a3), "r"(b0), "r"(b1));
}

__device__ __forceinline__ void cp_async16(void* smem, const void* gmem) {
    uint32_t s = (uint32_t)__cvta_generic_to_shared(smem);
    asm volatile("cp.async.cg.shared.global [%0], [%1], 16;" :: "r"(s), "l"(gmem));
}
#define CP_COMMIT asm volatile("cp.async.commit_group;")
#define CP_WAIT0  asm volatile("cp.async.wait_group 0;")
#define CP_WAIT1  asm volatile("cp.async.wait_group 1;")

// ---------------- mask -> additive bias, with dtype autodetect --------------
__global__ void __launch_bounds__(256) mask_bias_kernel(
    const unsigned char* __restrict__ m8, const unsigned char* __restrict__ s8)
{
    __shared__ int flag_off, flag_f32;
    if (threadIdx.x == 0) { flag_off = 0; flag_f32 = 0; }
    __syncthreads();

    int loc_off = 0, loc_f32 = 0;
    for (int p = threadIdx.x; p < BB * SS; p += blockDim.x) {
        unsigned char bm = m8[p];
        unsigned char bs = s8[p];
        if ((p & 3) != 0) {
            if (bm | bs) loc_off = 1;
            if (bm == 0x3f || bm == 0x80 || bs == 0x3f || bs == 0x80) loc_f32 = 1;
        }
    }
    if (loc_off) atomicOr(&flag_off, 1);
    if (loc_f32) atomicOr(&flag_f32, 1);
    __syncthreads();

    int code = flag_f32 ? 2 : (flag_off ? 0 : 1);  // 0=bool8, 1=int32, 2=f32

    for (int i = threadIdx.x; i < BB * SS; i += blockDim.x) {
        bool mv, sv;
        if (code == 0) {
            mv = m8[i] != 0;
            sv = s8[i] != 0;
        } else if (code == 1) {
            mv = ((const int*)m8)[i] != 0;
            sv = ((const int*)s8)[i] != 0;
        } else {
            mv = ((const float*)m8)[i] != 0.0f;
            sv = ((const float*)s8)[i] != 0.0f;
        }
        g_bias[i] = (mv || sv) ? -1e9f : 0.0f;
    }
}

// ---------------- tf32 tensor-core GEMM: C = A[M,K] * W[N,K]^T + bias[N] ----
#define BM 128
#define BN 128
#define BKG 16
#define SPAD 20

__global__ void __launch_bounds__(256) gemm_tf32(
    const float* __restrict__ A, const float* __restrict__ W,
    const float* __restrict__ bias, float* __restrict__ C, int roundOut)
{
    const int K = 1024, N = 1024;
    __shared__ float As[2][BM * SPAD];
    __shared__ float Ws[2][BN * SPAD];

    int tid  = threadIdx.x;
    int bn   = blockIdx.x * BN;
    int bm   = blockIdx.y * BM;
    int warp = tid >> 5, lane = tid & 31;
    int r = lane >> 2, g = lane & 3;
    int wm = (warp >> 1) * 32;
    int wn = (warp & 1) * 64;

    float acc[2][8][4];
#pragma unroll
    for (int mi = 0; mi < 2; mi++)
#pragma unroll
        for (int ni = 0; ni < 8; ni++)
#pragma unroll
            for (int e = 0; e < 4; e++) acc[mi][ni][e] = 0.0f;

    {
#pragma unroll
        for (int u = 0; u < 2; u++) {
            int ch  = tid + u * 256;
            int row = ch >> 2;
            int kc  = (ch & 3) * 4;
            cp_async16(&As[0][row * SPAD + kc], &A[(size_t)(bm + row) * K + kc]);
            cp_async16(&Ws[0][row * SPAD + kc], &W[(size_t)(bn + row) * K + kc]);
        }
        CP_COMMIT;
    }

    int buf = 0;
    for (int k0 = 0; k0 < K; k0 += BKG) {
        CP_WAIT0;
        __syncthreads();

        if (k0 + BKG < K) {
            int nb = buf ^ 1;
            int kn = k0 + BKG;
#pragma unroll
            for (int u = 0; u < 2; u++) {
                int ch  = tid + u * 256;
                int row = ch >> 2;
                int kc  = (ch & 3) * 4;
                cp_async16(&As[nb][row * SPAD + kc], &A[(size_t)(bm + row) * K + kn + kc]);
                cp_async16(&Ws[nb][row * SPAD + kc], &W[(size_t)(bn + row) * K + kn + kc]);
            }
            CP_COMMIT;
        }

        const float* as = As[buf];
        const float* ws = Ws[buf];
#pragma unroll
        for (int kk = 0; kk < BKG; kk += 8) {
            uint32_t a[2][4];
#pragma unroll
            for (int mi = 0; mi < 2; mi++) {
                int base = (wm + mi * 16 + r) * SPAD + kk + g;
                a[mi][0] = f2tf(as[base]);
                a[mi][1] = f2tf(as[base + 8 * SPAD]);
                a[mi][2] = f2tf(as[base + 4]);
                a[mi][3] = f2tf(as[base + 8 * SPAD + 4]);
            }
            uint32_t b[8][2];
#pragma unroll
            for (int ni = 0; ni < 8; ni++) {
                int base = (wn + ni * 8 + r) * SPAD + kk + g;
                b[ni][0] = f2tf(ws[base]);
                b[ni][1] = f2tf(ws[base + 4]);
            }
#pragma unroll
            for (int mi = 0; mi < 2; mi++)
#pragma unroll
                for (int ni = 0; ni < 8; ni++)
                    mma_tf32(acc[mi][ni], a[mi][0], a[mi][1], a[mi][2], a[mi][3],
                             b[ni][0], b[ni][1]);
        }
        buf ^= 1;
    }

#pragma unroll
    for (int mi = 0; mi < 2; mi++) {
        int row0 = bm + wm + mi * 16 + r;
#pragma unroll
        for (int ni = 0; ni < 8; ni++) {
            int col = bn + wn + ni * 8 + 2 * g;
            float b0 = bias[col], b1 = bias[col + 1];
            float2 v0, v1;
            v0.x = acc[mi][ni][0] + b0;
            v0.y = acc[mi][ni][1] + b1;
            v1.x = acc[mi][ni][2] + b0;
            v1.y = acc[mi][ni][3] + b1;
            if (roundOut) {  // pre-round to tf32 so attention can skip cvt
                v0.x = __uint_as_float(f2tf(v0.x));
                v0.y = __uint_as_float(f2tf(v0.y));
                v1.x = __uint_as_float(f2tf(v1.x));
                v1.y = __uint_as_float(f2tf(v1.y));
            }
            *(float2*)&C[(size_t)row0 * N + col]       = v0;
            *(float2*)&C[(size_t)(row0 + 8) * N + col] = v1;
        }
    }
}

// ---------------- tensor-core flash attention (static smem only) ------------
// grid (B*H, S/128), 256 threads = 8 warps; warp w owns q rows w*16..w*16+15.
// K-tiles of 64 keys. Static smem: sK + sV (34KB). P kept in registers; the
// C-frag -> A-frag conversion for P*V is done with shfl.sync (no smem P).
// Pipeline: V(t) loads during S-compute; K(t+1) loads during P*V.
#define AQ  128
#define AK  64
#define AST 68   // row stride (floats), 68 % 32 == 4 -> conflict-free frags
#define KV_TILE (AK * AST)

__global__ void __launch_bounds__(256) attn_kernel()
{
    __shared__ float sK[KV_TILE];
    __shared__ float sV[KV_TILE];

    int tid  = threadIdx.x;
    int warp = tid >> 5, lane = tid & 31;
    int r = lane >> 2, g = lane & 3;
    int b  = blockIdx.x >> 4;
    int h  = blockIdx.x & 15;
    int q0 = blockIdx.y * AQ;
    int w16 = warp * 16;
    const int bSS = b * SS;

    // ---- Q fragments straight from gmem (pre-rounded to tf32, L2-hot) ----
    uint32_t aq[8][4];
    {
        const float* q0p = g_qp + (size_t)(bSS + q0 + w16 + r) * DD + h * DH;
        const float* q1p = q0p + 8 * DD;
#pragma unroll
        for (int ks = 0; ks < 8; ks++) {
            int c = ks * 8 + g;
            aq[ks][0] = __float_as_uint(__ldg(&q0p[c]));
            aq[ks][1] = __float_as_uint(__ldg(&q1p[c]));
            aq[ks][2] = __float_as_uint(__ldg(&q0p[c + 4]));
            aq[ks][3] = __float_as_uint(__ldg(&q1p[c + 4]));
        }
    }

    // ---- prefetch K tile 0 ----
    for (int cch = tid; cch < AK * 16; cch += 256) {
        int row = cch >> 4;
        int c4  = (cch & 15) * 4;
        cp_async16(&sK[row * AST + c4],
                   &g_kp[(size_t)(bSS + row) * DD + h * DH + c4]);
    }
    CP_COMMIT;

    float o[8][4];
#pragma unroll
    for (int nt = 0; nt < 8; nt++)
#pragma unroll
        for (int e = 0; e < 4; e++) o[nt][e] = 0.0f;
    float m0 = -INFINITY, m1 = -INFINITY, l0 = 0.0f, l1 = 0.0f;

    const int shufL0 = (r << 2) + (g >> 1);
    const int shufL1 = shufL0 + 2;
    const bool oddg  = (g & 1);

    const int NT = SS / AK;  // 16
    for (int t = 0; t < NT; t++) {
        if (t > 0) __syncthreads();   // prior PV done with sV before overwrite

        // issue V(t)
        for (int cch = tid; cch < AK * 16; cch += 256) {
            int row = cch >> 4;
            int c4  = (cch & 15) * 4;
            cp_async16(&sV[row * AST + c4],
                       &g_vp[(size_t)(bSS + t * AK + row) * DD + h * DH + c4]);
        }
        CP_COMMIT;

        CP_WAIT1;          // K(t) landed (V(t) may still be in flight)
        __syncthreads();

        // ---- scores S = Q K^T ----
        float s[8][4];
#pragma unroll
        for (int nt = 0; nt < 8; nt++)
#pragma unroll
            for (int e = 0; e < 4; e++) s[nt][e] = 0.0f;

#pragma unroll
        for (int ks = 0; ks < 8; ks++) {
#pragma unroll
            for (int nt = 0; nt < 8; nt++) {
                int base = (nt * 8 + r) * AST + ks * 8 + g;
                uint32_t b0 = __float_as_uint(sK[base]);
                uint32_t b1 = __float_as_uint(sK[base + 4]);
                mma_tf32(s[nt], aq[ks][0], aq[ks][1], aq[ks][2], aq[ks][3], b0, b1);
            }
        }

        // ---- online softmax on fragments; P -> tf32 bits in registers ----
        int k0 = t * AK;
        float mx0 = -INFINITY, mx1 = -INFINITY;
#pragma unroll
        for (int nt = 0; nt < 8; nt++) {
            int col = k0 + nt * 8 + 2 * g;
            float bv0 = g_bias[bSS + col];
            float bv1 = g_bias[bSS + col + 1];
            s[nt][0] = s[nt][0] * 0.125f + bv0;
            s[nt][1] = s[nt][1] * 0.125f + bv1;
            s[nt][2] = s[nt][2] * 0.125f + bv0;
            s[nt][3] = s[nt][3] * 0.125f + bv1;
            mx0 = fmaxf(mx0, fmaxf(s[nt][0], s[nt][1]));
            mx1 = fmaxf(mx1, fmaxf(s[nt][2], s[nt][3]));
        }
        mx0 = fmaxf(mx0, __shfl_xor_sync(0xffffffffu, mx0, 1));
        mx0 = fmaxf(mx0, __shfl_xor_sync(0xffffffffu, mx0, 2));
        mx1 = fmaxf(mx1, __shfl_xor_sync(0xffffffffu, mx1, 1));
        mx1 = fmaxf(mx1, __shfl_xor_sync(0xffffffffu, mx1, 2));

        float m0n = fmaxf(m0, mx0), m1n = fmaxf(m1, mx1);
        float c0 = __expf(m0 - m0n), c1 = __expf(m1 - m1n);
        m0 = m0n; m1 = m1n;

        uint32_t pt[8][4];
        float sum0 = 0.0f, sum1 = 0.0f;
#pragma unroll
        for (int nt = 0; nt < 8; nt++) {
            float p00 = __expf(s[nt][0] - m0);
            float p01 = __expf(s[nt][1] - m0);
            float p10 = __expf(s[nt][2] - m1);
            float p11 = __expf(s[nt][3] - m1);
            sum0 += p00 + p01;
            sum1 += p10 + p11;
            pt[nt][0] = f2tf(p00);
            pt[nt][1] = f2tf(p01);
            pt[nt][2] = f2tf(p10);
            pt[nt][3] = f2tf(p11);
        }
        sum0 += __shfl_xor_sync(0xffffffffu, sum0, 1);
        sum0 += __shfl_xor_sync(0xffffffffu, sum0, 2);
        sum1 += __shfl_xor_sync(0xffffffffu, sum1, 1);
        sum1 += __shfl_xor_sync(0xffffffffu, sum1, 2);
        l0 = l0 * c0 + sum0;
        l1 = l1 * c1 + sum1;

#pragma unroll
        for (int nt = 0; nt < 8; nt++) {
            o[nt][0] *= c0; o[nt][1] *= c0;
            o[nt][2] *= c1; o[nt][3] *= c1;
        }

        __syncthreads();   // all warps done reading sK -> safe to refill
        if (t + 1 < NT) {
            for (int cch = tid; cch < AK * 16; cch += 256) {
                int row = cch >> 4;
                int c4  = (cch & 15) * 4;
                cp_async16(&sK[row * AST + c4],
                           &g_kp[(size_t)(bSS + (t + 1) * AK + row) * DD + h * DH + c4]);
            }
            CP_COMMIT;
            CP_WAIT1;      // V(t) done (K(t+1) in flight)
        } else {
            CP_WAIT0;      // V(t) done
        }
        __syncthreads();

        // ---- O += P V : A-frag of P built via shfl from C-frags ----
#pragma unroll
        for (int ks = 0; ks < 8; ks++) {
            uint32_t u0 = __shfl_sync(0xffffffffu, pt[ks][0], shufL0);
            uint32_t u1 = __shfl_sync(0xffffffffu, pt[ks][1], shufL0);
            uint32_t v0 = __shfl_sync(0xffffffffu, pt[ks][2], shufL0);
            uint32_t v1 = __shfl_sync(0xffffffffu, pt[ks][3], shufL0);
            uint32_t w0 = __shfl_sync(0xffffffffu, pt[ks][0], shufL1);
            uint32_t w1 = __shfl_sync(0xffffffffu, pt[ks][1], shufL1);
            uint32_t x0 = __shfl_sync(0xffffffffu, pt[ks][2], shufL1);
            uint32_t x1 = __shfl_sync(0xffffffffu, pt[ks][3], shufL1);
            uint32_t a0 = oddg ? u1 : u0;
            uint32_t a1 = oddg ? v1 : v0;
            uint32_t a2 = oddg ? w1 : w0;
            uint32_t a3 = oddg ? x1 : x0;
#pragma unroll
            for (int nt = 0; nt < 8; nt++) {
                uint32_t b0 = __float_as_uint(sV[(ks * 8 + g) * AST + nt * 8 + r]);
                uint32_t b1 = __float_as_uint(sV[(ks * 8 + g + 4) * AST + nt * 8 + r]);
                mma_tf32(o[nt], a0, a1, a2, a3, b0, b1);
            }
        }
    }

    // ---- normalize + write [B,S,D] merged heads ----
    float inv0 = 1.0f / l0, inv1 = 1.0f / l1;
#pragma unroll
    for (int nt = 0; nt < 8; nt++) {
        int col = h * DH + nt * 8 + 2 * g;
        float2 w0, w1;
        w0.x = o[nt][0] * inv0; w0.y = o[nt][1] * inv0;
        w1.x = o[nt][2] * inv1; w1.y = o[nt][3] * inv1;
        *(float2*)&g_attn[(size_t)(bSS + q0 + w16 + r) * DD + col]     = w0;
        *(float2*)&g_attn[(size_t)(bSS + q0 + w16 + r + 8) * DD + col] = w1;
    }
}

// ---------------- launch -----------------------------------------------------
extern "C" void kernel_launch(void* const* d_in, const int* in_sizes, int n_in,
                              void* d_out, int out_size)
{
    const float* v  = (const float*)d_in[0];
    const float* k  = (const float*)d_in[1];
    const float* q  = (const float*)d_in[2];
    const unsigned char* mask   = (const unsigned char*)d_in[3];
    const unsigned char* semask = (const unsigned char*)d_in[4];
    const float* Wv = (const float*)d_in[5];
    const float* bv = (const float*)d_in[6];
    const float* Wk = (const float*)d_in[7];
    const float* bk = (const float*)d_in[8];
    const float* Wq = (const float*)d_in[9];
    const float* bq = (const float*)d_in[10];
    const float* Wm = (const float*)d_in[11];
    const float* bm = (const float*)d_in[12];
    float* out = (float*)d_out;

    float *pq, *pk, *pv, *pa;
    cudaGetSymbolAddress((void**)&pq, g_qp);
    cudaGetSymbolAddress((void**)&pk, g_kp);
    cudaGetSymbolAddress((void**)&pv, g_vp);
    cudaGetSymbolAddress((void**)&pa, g_attn);

    mask_bias_kernel<<<1, 256>>>(mask, semask);

    dim3 gg(1024 / BN, MR / BM);  // (8, 32)
    gemm_tf32<<<gg, 256>>>(v, Wv, bv, pv, 1);
    gemm_tf32<<<gg, 256>>>(k, Wk, bk, pk, 1);
    gemm_tf32<<<gg, 256>>>(q, Wq, bq, pq, 1);

    attn_kernel<<<dim3(BB * HH, SS / AQ), 256>>>();

    gemm_tf32<<<gg, 256>>>(pa, Wm, bm, out, 0);
}

// round 6
// speedup vs baseline: 2.7467x; 1.0522x over previous
#include <cuda_runtime.h>
#include <math.h>
#include <stdint.h>

// Problem constants
#define BB 4
#define SS 1024
#define DD 1024
#define HH 16
#define DH 64
#define MR (BB * SS)   // 4096 rows

// ---------------- scratch (static device globals; allocation-free) ----------
__device__ float g_qp[MR * DD];
__device__ float g_kp[MR * DD];
__device__ float g_vp[MR * DD];
__device__ float g_attn[MR * DD];
__device__ float g_bias[BB * SS];
__device__ float g_rin[3 * MR * DD];   // tf32-rounded v,k,q
__device__ float g_rw[4 * DD * DD];    // tf32-rounded Wv,Wk,Wq,Wm

// ---------------- small PTX helpers -----------------------------------------
__device__ __forceinline__ uint32_t f2tf(float x) {
    uint32_t r;
    asm("cvt.rna.tf32.f32 %0, %1;" : "=r"(r) : "f"(x));
    return r;
}
__device__ __forceinline__ float f2tff(float x) { return __uint_as_float(f2tf(x)); }

__device__ __forceinline__ void mma_tf32(float c[4],
                                         uint32_t a0, uint32_t a1, uint32_t a2, uint32_t a3,
                                         uint32_t b0, uint32_t b1) {
    asm volatile(
        "mma.sync.aligned.m16n8k8.row.col.f32.tf32.tf32.f32 "
        "{%0,%1,%2,%3}, {%4,%5,%6,%7}, {%8,%9}, {%0,%1,%2,%3};"
        : "+f"(c[0]), "+f"(c[1]), "+f"(c[2]), "+f"(c[3])
        : "r"(a0), "r"(a1), "r"(a2), "r"(a3), "r"(b0), "r"(b1));
}

__device__ __forceinline__ void cp_async16(void* smem, const void* gmem) {
    uint32_t s = (uint32_t)__cvta_generic_to_shared(smem);
    asm volatile("cp.async.cg.shared.global [%0], [%1], 16;" :: "r"(s), "l"(gmem));
}
#define CP_COMMIT asm volatile("cp.async.commit_group;")
#define CP_WAIT0  asm volatile("cp.async.wait_group 0;")
#define CP_WAIT1  asm volatile("cp.async.wait_group 1;")

// ---------------- mask -> additive bias, with dtype autodetect --------------
__global__ void __launch_bounds__(256) mask_bias_kernel(
    const unsigned char* __restrict__ m8, const unsigned char* __restrict__ s8)
{
    __shared__ int flag_off, flag_f32;
    if (threadIdx.x == 0) { flag_off = 0; flag_f32 = 0; }
    __syncthreads();

    int loc_off = 0, loc_f32 = 0;
    for (int p = threadIdx.x; p < BB * SS; p += blockDim.x) {
        unsigned char bm = m8[p];
        unsigned char bs = s8[p];
        if ((p & 3) != 0) {
            if (bm | bs) loc_off = 1;
            if (bm == 0x3f || bm == 0x80 || bs == 0x3f || bs == 0x80) loc_f32 = 1;
        }
    }
    if (loc_off) atomicOr(&flag_off, 1);
    if (loc_f32) atomicOr(&flag_f32, 1);
    __syncthreads();

    int code = flag_f32 ? 2 : (flag_off ? 0 : 1);  // 0=bool8, 1=int32, 2=f32

    for (int i = threadIdx.x; i < BB * SS; i += blockDim.x) {
        bool mv, sv;
        if (code == 0) {
            mv = m8[i] != 0;
            sv = s8[i] != 0;
        } else if (code == 1) {
            mv = ((const int*)m8)[i] != 0;
            sv = ((const int*)s8)[i] != 0;
        } else {
            mv = ((const float*)m8)[i] != 0.0f;
            sv = ((const float*)s8)[i] != 0.0f;
        }
        g_bias[i] = (mv || sv) ? -1e9f : 0.0f;
    }
}

// ---------------- pre-round v,k,q + all weights to tf32 ---------------------
#define F4BIG (MR * DD / 4)   // 1048576 float4 per big tensor
#define F4W   (DD * DD / 4)   // 262144 float4 per weight

__global__ void __launch_bounds__(256) round_all(
    const float4* __restrict__ v, const float4* __restrict__ k,
    const float4* __restrict__ q,
    const float4* __restrict__ Wv, const float4* __restrict__ Wk,
    const float4* __restrict__ Wq, const float4* __restrict__ Wm)
{
    size_t t = (size_t)blockIdx.x * blockDim.x + threadIdx.x;
    const float4* src;
    float4* dst;
    if (t < F4BIG) {
        src = v + t;                         dst = (float4*)g_rin + t;
    } else if (t < 2 * (size_t)F4BIG) {
        src = k + (t - F4BIG);               dst = (float4*)g_rin + t;
    } else if (t < 3 * (size_t)F4BIG) {
        src = q + (t - 2 * F4BIG);           dst = (float4*)g_rin + t;
    } else {
        size_t tw  = t - 3 * (size_t)F4BIG;
        int    seg = (int)(tw / F4W);
        size_t off = tw - (size_t)seg * F4W;
        const float4* ws[4] = { Wv, Wk, Wq, Wm };
        src = ws[seg] + off;
        dst = (float4*)g_rw + tw;
    }
    float4 a = *src;
    a.x = f2tff(a.x); a.y = f2tff(a.y); a.z = f2tff(a.z); a.w = f2tff(a.w);
    *dst = a;
}

// ---------------- tf32 tensor-core GEMM body (inputs pre-rounded) -----------
#define BM 128
#define BN 128
#define BKG 16
#define SPAD 20

__device__ __forceinline__ void gemm_body(
    const float* __restrict__ A, const float* __restrict__ W,
    const float* __restrict__ bias, float* __restrict__ C, int roundOut)
{
    const int K = 1024, N = 1024;
    __shared__ float As[2][BM * SPAD];
    __shared__ float Ws[2][BN * SPAD];

    int tid  = threadIdx.x;
    int bn   = blockIdx.x * BN;
    int bm   = blockIdx.y * BM;
    int warp = tid >> 5, lane = tid & 31;
    int r = lane >> 2, g = lane & 3;
    int wm = (warp >> 1) * 32;
    int wn = (warp & 1) * 64;

    float acc[2][8][4];
#pragma unroll
    for (int mi = 0; mi < 2; mi++)
#pragma unroll
        for (int ni = 0; ni < 8; ni++)
#pragma unroll
            for (int e = 0; e < 4; e++) acc[mi][ni][e] = 0.0f;

    {
#pragma unroll
        for (int u = 0; u < 2; u++) {
            int ch  = tid + u * 256;
            int row = ch >> 2;
            int kc  = (ch & 3) * 4;
            cp_async16(&As[0][row * SPAD + kc], &A[(size_t)(bm + row) * K + kc]);
            cp_async16(&Ws[0][row * SPAD + kc], &W[(size_t)(bn + row) * K + kc]);
        }
        CP_COMMIT;
    }

    int buf = 0;
    for (int k0 = 0; k0 < K; k0 += BKG) {
        CP_WAIT0;
        __syncthreads();

        if (k0 + BKG < K) {
            int nb = buf ^ 1;
            int kn = k0 + BKG;
#pragma unroll
            for (int u = 0; u < 2; u++) {
                int ch  = tid + u * 256;
                int row = ch >> 2;
                int kc  = (ch & 3) * 4;
                cp_async16(&As[nb][row * SPAD + kc], &A[(size_t)(bm + row) * K + kn + kc]);
                cp_async16(&Ws[nb][row * SPAD + kc], &W[(size_t)(bn + row) * K + kn + kc]);
            }
            CP_COMMIT;
        }

        const float* as = As[buf];
        const float* ws = Ws[buf];
#pragma unroll
        for (int kk = 0; kk < BKG; kk += 8) {
            uint32_t a[2][4];
#pragma unroll
            for (int mi = 0; mi < 2; mi++) {
                int base = (wm + mi * 16 + r) * SPAD + kk + g;
                a[mi][0] = __float_as_uint(as[base]);
                a[mi][1] = __float_as_uint(as[base + 8 * SPAD]);
                a[mi][2] = __float_as_uint(as[base + 4]);
                a[mi][3] = __float_as_uint(as[base + 8 * SPAD + 4]);
            }
            uint32_t b[8][2];
#pragma unroll
            for (int ni = 0; ni < 8; ni++) {
                int base = (wn + ni * 8 + r) * SPAD + kk + g;
                b[ni][0] = __float_as_uint(ws[base]);
                b[ni][1] = __float_as_uint(ws[base + 4]);
            }
#pragma unroll
            for (int mi = 0; mi < 2; mi++)
#pragma unroll
                for (int ni = 0; ni < 8; ni++)
                    mma_tf32(acc[mi][ni], a[mi][0], a[mi][1], a[mi][2], a[mi][3],
                             b[ni][0], b[ni][1]);
        }
        buf ^= 1;
    }

#pragma unroll
    for (int mi = 0; mi < 2; mi++) {
        int row0 = bm + wm + mi * 16 + r;
#pragma unroll
        for (int ni = 0; ni < 8; ni++) {
            int col = bn + wn + ni * 8 + 2 * g;
            float b0 = bias[col], b1 = bias[col + 1];
            float2 v0, v1;
            v0.x = acc[mi][ni][0] + b0;
            v0.y = acc[mi][ni][1] + b1;
            v1.x = acc[mi][ni][2] + b0;
            v1.y = acc[mi][ni][3] + b1;
            if (roundOut) {  // pre-round to tf32 for downstream tensor ops
                v0.x = f2tff(v0.x); v0.y = f2tff(v0.y);
                v1.x = f2tff(v1.x); v1.y = f2tff(v1.y);
            }
            *(float2*)&C[(size_t)row0 * N + col]       = v0;
            *(float2*)&C[(size_t)(row0 + 8) * N + col] = v1;
        }
    }
}

// fused QKV projections: blockIdx.z selects {v,k,q}
__global__ void __launch_bounds__(256) gemm_qkv(
    const float* __restrict__ bv, const float* __restrict__ bk,
    const float* __restrict__ bq,
    float* __restrict__ pv, float* __restrict__ pk, float* __restrict__ pq)
{
    int z = blockIdx.z;
    const float* A    = g_rin + (size_t)z * MR * DD;
    const float* W    = g_rw  + (size_t)z * DD * DD;
    const float* bias = (z == 0) ? bv : (z == 1) ? bk : bq;
    float*       C    = (z == 0) ? pv : (z == 1) ? pk : pq;
    gemm_body(A, W, bias, C, 1);
}

// output projection
__global__ void __launch_bounds__(256) gemm_out(
    const float* __restrict__ A, const float* __restrict__ bias,
    float* __restrict__ C)
{
    gemm_body(A, g_rw + 3 * (size_t)DD * DD, bias, C, 0);
}

// ---------------- tensor-core flash attention (static smem only) ------------
#define AQ  128
#define AK  64
#define AST 68
#define KV_TILE (AK * AST)

__global__ void __launch_bounds__(256) attn_kernel()
{
    __shared__ float sK[KV_TILE];
    __shared__ float sV[KV_TILE];

    int tid  = threadIdx.x;
    int warp = tid >> 5, lane = tid & 31;
    int r = lane >> 2, g = lane & 3;
    int b  = blockIdx.x >> 4;
    int h  = blockIdx.x & 15;
    int q0 = blockIdx.y * AQ;
    int w16 = warp * 16;
    const int bSS = b * SS;

    uint32_t aq[8][4];
    {
        const float* q0p = g_qp + (size_t)(bSS + q0 + w16 + r) * DD + h * DH;
        const float* q1p = q0p + 8 * DD;
#pragma unroll
        for (int ks = 0; ks < 8; ks++) {
            int c = ks * 8 + g;
            aq[ks][0] = __float_as_uint(__ldg(&q0p[c]));
            aq[ks][1] = __float_as_uint(__ldg(&q1p[c]));
            aq[ks][2] = __float_as_uint(__ldg(&q0p[c + 4]));
            aq[ks][3] = __float_as_uint(__ldg(&q1p[c + 4]));
        }
    }

    for (int cch = tid; cch < AK * 16; cch += 256) {
        int row = cch >> 4;
        int c4  = (cch & 15) * 4;
        cp_async16(&sK[row * AST + c4],
                   &g_kp[(size_t)(bSS + row) * DD + h * DH + c4]);
    }
    CP_COMMIT;

    float o[8][4];
#pragma unroll
    for (int nt = 0; nt < 8; nt++)
#pragma unroll
        for (int e = 0; e < 4; e++) o[nt][e] = 0.0f;
    float m0 = -INFINITY, m1 = -INFINITY, l0 = 0.0f, l1 = 0.0f;

    const int shufL0 = (r << 2) + (g >> 1);
    const int shufL1 = shufL0 + 2;
    const bool oddg  = (g & 1);

    const int NT = SS / AK;  // 16
    for (int t = 0; t < NT; t++) {
        if (t > 0) __syncthreads();

        for (int cch = tid; cch < AK * 16; cch += 256) {
            int row = cch >> 4;
            int c4  = (cch & 15) * 4;
            cp_async16(&sV[row * AST + c4],
                       &g_vp[(size_t)(bSS + t * AK + row) * DD + h * DH + c4]);
        }
        CP_COMMIT;

        CP_WAIT1;
        __syncthreads();

        float s[8][4];
#pragma unroll
        for (int nt = 0; nt < 8; nt++)
#pragma unroll
            for (int e = 0; e < 4; e++) s[nt][e] = 0.0f;

#pragma unroll
        for (int ks = 0; ks < 8; ks++) {
#pragma unroll
            for (int nt = 0; nt < 8; nt++) {
                int base = (nt * 8 + r) * AST + ks * 8 + g;
                uint32_t b0 = __float_as_uint(sK[base]);
                uint32_t b1 = __float_as_uint(sK[base + 4]);
                mma_tf32(s[nt], aq[ks][0], aq[ks][1], aq[ks][2], aq[ks][3], b0, b1);
            }
        }

        int k0 = t * AK;
        float mx0 = -INFINITY, mx1 = -INFINITY;
#pragma unroll
        for (int nt = 0; nt < 8; nt++) {
            int col = k0 + nt * 8 + 2 * g;
            float bv0 = g_bias[bSS + col];
            float bv1 = g_bias[bSS + col + 1];
            s[nt][0] = s[nt][0] * 0.125f + bv0;
            s[nt][1] = s[nt][1] * 0.125f + bv1;
            s[nt][2] = s[nt][2] * 0.125f + bv0;
            s[nt][3] = s[nt][3] * 0.125f + bv1;
            mx0 = fmaxf(mx0, fmaxf(s[nt][0], s[nt][1]));
            mx1 = fmaxf(mx1, fmaxf(s[nt][2], s[nt][3]));
        }
        mx0 = fmaxf(mx0, __shfl_xor_sync(0xffffffffu, mx0, 1));
        mx0 = fmaxf(mx0, __shfl_xor_sync(0xffffffffu, mx0, 2));
        mx1 = fmaxf(mx1, __shfl_xor_sync(0xffffffffu, mx1, 1));
        mx1 = fmaxf(mx1, __shfl_xor_sync(0xffffffffu, mx1, 2));

        float m0n = fmaxf(m0, mx0), m1n = fmaxf(m1, mx1);
        float c0 = __expf(m0 - m0n), c1 = __expf(m1 - m1n);
        m0 = m0n; m1 = m1n;

        uint32_t pt[8][4];
        float sum0 = 0.0f, sum1 = 0.0f;
#pragma unroll
        for (int nt = 0; nt < 8; nt++) {
            float p00 = __expf(s[nt][0] - m0);
            float p01 = __expf(s[nt][1] - m0);
            float p10 = __expf(s[nt][2] - m1);
            float p11 = __expf(s[nt][3] - m1);
            sum0 += p00 + p01;
            sum1 += p10 + p11;
            pt[nt][0] = f2tf(p00);
            pt[nt][1] = f2tf(p01);
            pt[nt][2] = f2tf(p10);
            pt[nt][3] = f2tf(p11);
        }
        sum0 += __shfl_xor_sync(0xffffffffu, sum0, 1);
        sum0 += __shfl_xor_sync(0xffffffffu, sum0, 2);
        sum1 += __shfl_xor_sync(0xffffffffu, sum1, 1);
        sum1 += __shfl_xor_sync(0xffffffffu, sum1, 2);
        l0 = l0 * c0 + sum0;
        l1 = l1 * c1 + sum1;

#pragma unroll
        for (int nt = 0; nt < 8; nt++) {
            o[nt][0] *= c0; o[nt][1] *= c0;
            o[nt][2] *= c1; o[nt][3] *= c1;
        }

        __syncthreads();
        if (t + 1 < NT) {
            for (int cch = tid; cch < AK * 16; cch += 256) {
                int row = cch >> 4;
                int c4  = (cch & 15) * 4;
                cp_async16(&sK[row * AST + c4],
                           &g_kp[(size_t)(bSS + (t + 1) * AK + row) * DD + h * DH + c4]);
            }
            CP_COMMIT;
            CP_WAIT1;
        } else {
            CP_WAIT0;
        }
        __syncthreads();

#pragma unroll
        for (int ks = 0; ks < 8; ks++) {
            uint32_t u0 = __shfl_sync(0xffffffffu, pt[ks][0], shufL0);
            uint32_t u1 = __shfl_sync(0xffffffffu, pt[ks][1], shufL0);
            uint32_t v0 = __shfl_sync(0xffffffffu, pt[ks][2], shufL0);
            uint32_t v1 = __shfl_sync(0xffffffffu, pt[ks][3], shufL0);
            uint32_t w0 = __shfl_sync(0xffffffffu, pt[ks][0], shufL1);
            uint32_t w1 = __shfl_sync(0xffffffffu, pt[ks][1], shufL1);
            uint32_t x0 = __shfl_sync(0xffffffffu, pt[ks][2], shufL1);
            uint32_t x1 = __shfl_sync(0xffffffffu, pt[ks][3], shufL1);
            uint32_t a0 = oddg ? u1 : u0;
            uint32_t a1 = oddg ? v1 : v0;
            uint32_t a2 = oddg ? w1 : w0;
            uint32_t a3 = oddg ? x1 : x0;
#pragma unroll
            for (int nt = 0; nt < 8; nt++) {
                uint32_t b0 = __float_as_uint(sV[(ks * 8 + g) * AST + nt * 8 + r]);
                uint32_t b1 = __float_as_uint(sV[(ks * 8 + g + 4) * AST + nt * 8 + r]);
                mma_tf32(o[nt], a0, a1, a2, a3, b0, b1);
            }
        }
    }

    // normalize + pre-round (final GEMM reads tf32) + write merged heads
    float inv0 = 1.0f / l0, inv1 = 1.0f / l1;
#pragma unroll
    for (int nt = 0; nt < 8; nt++) {
        int col = h * DH + nt * 8 + 2 * g;
        float2 w0, w1;
        w0.x = f2tff(o[nt][0] * inv0); w0.y = f2tff(o[nt][1] * inv0);
        w1.x = f2tff(o[nt][2] * inv1); w1.y = f2tff(o[nt][3] * inv1);
        *(float2*)&g_attn[(size_t)(bSS + q0 + w16 + r) * DD + col]     = w0;
        *(float2*)&g_attn[(size_t)(bSS + q0 + w16 + r + 8) * DD + col] = w1;
    }
}

// ---------------- launch -----------------------------------------------------
extern "C" void kernel_launch(void* const* d_in, const int* in_sizes, int n_in,
                              void* d_out, int out_size)
{
    const float* v  = (const float*)d_in[0];
    const float* k  = (const float*)d_in[1];
    const float* q  = (const float*)d_in[2];
    const unsigned char* mask   = (const unsigned char*)d_in[3];
    const unsigned char* semask = (const unsigned char*)d_in[4];
    const float* Wv = (const float*)d_in[5];
    const float* bv = (const float*)d_in[6];
    const float* Wk = (const float*)d_in[7];
    const float* bk = (const float*)d_in[8];
    const float* Wq = (const float*)d_in[9];
    const float* bq = (const float*)d_in[10];
    const float* Wm = (const float*)d_in[11];
    const float* bm = (const float*)d_in[12];
    float* out = (float*)d_out;

    float *pq, *pk, *pv, *pa;
    cudaGetSymbolAddress((void**)&pq, g_qp);
    cudaGetSymbolAddress((void**)&pk, g_kp);
    cudaGetSymbolAddress((void**)&pv, g_vp);
    cudaGetSymbolAddress((void**)&pa, g_attn);

    mask_bias_kernel<<<1, 256>>>(mask, semask);

    // round v,k,q + all weights to tf32 (16M floats = 4M float4)
    round_all<<<(3 * F4BIG + 4 * F4W) / 256, 256>>>(
        (const float4*)v, (const float4*)k, (const float4*)q,
        (const float4*)Wv, (const float4*)Wk, (const float4*)Wq,
        (const float4*)Wm);

    dim3 gg(1024 / BN, MR / BM, 3);  // (8, 32, 3) fused QKV
    gemm_qkv<<<gg, 256>>>(bv, bk, bq, pv, pk, pq);

    attn_kernel<<<dim3(BB * HH, SS / AQ), 256>>>();

    gemm_out<<<dim3(1024 / BN, MR / BM), 256>>>(pa, bm, out);
}

// round 7
// speedup vs baseline: 3.4003x; 1.2380x over previous
#include <cuda_runtime.h>
#include <cuda_fp16.h>
#include <math.h>
#include <stdint.h>

// Problem constants
#define BB 4
#define SS 1024
#define DD 1024
#define HH 16
#define DH 64
#define MR (BB * SS)   // 4096 rows

// ---------------- scratch (static device globals; allocation-free) ----------
__device__ __half g_qh[MR * DD];
__device__ __half g_kh[MR * DD];
__device__ __half g_vh[MR * DD];
__device__ float  g_attn[MR * DD];
__device__ float  g_bias[BB * SS];
__device__ float  g_rin[3 * MR * DD];   // tf32-rounded v,k,q
__device__ float  g_rw[4 * DD * DD];    // tf32-rounded Wv,Wk,Wq,Wm

// ---------------- small PTX helpers -----------------------------------------
__device__ __forceinline__ uint32_t f2tf(float x) {
    uint32_t r;
    asm("cvt.rna.tf32.f32 %0, %1;" : "=r"(r) : "f"(x));
    return r;
}
__device__ __forceinline__ float f2tff(float x) { return __uint_as_float(f2tf(x)); }

__device__ __forceinline__ uint32_t pack_h2(float lo, float hi) {
    uint32_t d;
    asm("cvt.rn.f16x2.f32 %0, %1, %2;" : "=r"(d) : "f"(hi), "f"(lo));
    return d;
}

__device__ __forceinline__ void mma_tf32(float c[4],
                                         uint32_t a0, uint32_t a1, uint32_t a2, uint32_t a3,
                                         uint32_t b0, uint32_t b1) {
    asm volatile(
        "mma.sync.aligned.m16n8k8.row.col.f32.tf32.tf32.f32 "
        "{%0,%1,%2,%3}, {%4,%5,%6,%7}, {%8,%9}, {%0,%1,%2,%3};"
        : "+f"(c[0]), "+f"(c[1]), "+f"(c[2]), "+f"(c[3])
        : "r"(a0), "r"(a1), "r"(a2), "r"(a3), "r"(b0), "r"(b1));
}

__device__ __forceinline__ void mma_f16(float c[4],
                                        uint32_t a0, uint32_t a1, uint32_t a2, uint32_t a3,
                                        uint32_t b0, uint32_t b1) {
    asm volatile(
        "mma.sync.aligned.m16n8k16.row.col.f32.f16.f16.f32 "
        "{%0,%1,%2,%3}, {%4,%5,%6,%7}, {%8,%9}, {%0,%1,%2,%3};"
        : "+f"(c[0]), "+f"(c[1]), "+f"(c[2]), "+f"(c[3])
        : "r"(a0), "r"(a1), "r"(a2), "r"(a3), "r"(b0), "r"(b1));
}

__device__ __forceinline__ void ldsm4(uint32_t r[4], uint32_t addr) {
    asm volatile("ldmatrix.sync.aligned.m8n8.x4.shared.b16 {%0,%1,%2,%3}, [%4];"
                 : "=r"(r[0]), "=r"(r[1]), "=r"(r[2]), "=r"(r[3]) : "r"(addr));
}
__device__ __forceinline__ void ldsm4t(uint32_t r[4], uint32_t addr) {
    asm volatile("ldmatrix.sync.aligned.m8n8.x4.trans.shared.b16 {%0,%1,%2,%3}, [%4];"
                 : "=r"(r[0]), "=r"(r[1]), "=r"(r[2]), "=r"(r[3]) : "r"(addr));
}

__device__ __forceinline__ void cp_async16(void* smem, const void* gmem) {
    uint32_t s = (uint32_t)__cvta_generic_to_shared(smem);
    asm volatile("cp.async.cg.shared.global [%0], [%1], 16;" :: "r"(s), "l"(gmem));
}
#define CP_COMMIT asm volatile("cp.async.commit_group;")
#define CP_WAIT0  asm volatile("cp.async.wait_group 0;")

// ---------------- mask -> additive bias, with dtype autodetect --------------
__global__ void __launch_bounds__(256) mask_bias_kernel(
    const unsigned char* __restrict__ m8, const unsigned char* __restrict__ s8)
{
    __shared__ int flag_off, flag_f32;
    if (threadIdx.x == 0) { flag_off = 0; flag_f32 = 0; }
    __syncthreads();

    int loc_off = 0, loc_f32 = 0;
    for (int p = threadIdx.x; p < BB * SS; p += blockDim.x) {
        unsigned char bm = m8[p];
        unsigned char bs = s8[p];
        if ((p & 3) != 0) {
            if (bm | bs) loc_off = 1;
            if (bm == 0x3f || bm == 0x80 || bs == 0x3f || bs == 0x80) loc_f32 = 1;
        }
    }
    if (loc_off) atomicOr(&flag_off, 1);
    if (loc_f32) atomicOr(&flag_f32, 1);
    __syncthreads();

    int code = flag_f32 ? 2 : (flag_off ? 0 : 1);  // 0=bool8, 1=int32, 2=f32

    for (int i = threadIdx.x; i < BB * SS; i += blockDim.x) {
        bool mv, sv;
        if (code == 0) {
            mv = m8[i] != 0;
            sv = s8[i] != 0;
        } else if (code == 1) {
            mv = ((const int*)m8)[i] != 0;
            sv = ((const int*)s8)[i] != 0;
        } else {
            mv = ((const float*)m8)[i] != 0.0f;
            sv = ((const float*)s8)[i] != 0.0f;
        }
        g_bias[i] = (mv || sv) ? -1e9f : 0.0f;
    }
}

// ---------------- pre-round v,k,q + all weights to tf32 ---------------------
#define F4BIG (MR * DD / 4)
#define F4W   (DD * DD / 4)

__global__ void __launch_bounds__(256) round_all(
    const float4* __restrict__ v, const float4* __restrict__ k,
    const float4* __restrict__ q,
    const float4* __restrict__ Wv, const float4* __restrict__ Wk,
    const float4* __restrict__ Wq, const float4* __restrict__ Wm)
{
    size_t t = (size_t)blockIdx.x * blockDim.x + threadIdx.x;
    const float4* src;
    float4* dst;
    if (t < F4BIG) {
        src = v + t;                         dst = (float4*)g_rin + t;
    } else if (t < 2 * (size_t)F4BIG) {
        src = k + (t - F4BIG);               dst = (float4*)g_rin + t;
    } else if (t < 3 * (size_t)F4BIG) {
        src = q + (t - 2 * F4BIG);           dst = (float4*)g_rin + t;
    } else {
        size_t tw  = t - 3 * (size_t)F4BIG;
        int    seg = (int)(tw / F4W);
        size_t off = tw - (size_t)seg * F4W;
        const float4* ws[4] = { Wv, Wk, Wq, Wm };
        src = ws[seg] + off;
        dst = (float4*)g_rw + tw;
    }
    float4 a = *src;
    a.x = f2tff(a.x); a.y = f2tff(a.y); a.z = f2tff(a.z); a.w = f2tff(a.w);
    *dst = a;
}

// ---------------- tf32 tensor-core GEMM body (inputs pre-rounded) -----------
#define BM 128
#define BN 128
#define BKG 16
#define SPAD 20

// mode 0: fp32 C out; mode 1: fp16 C out (packed half2)
__device__ __forceinline__ void gemm_body(
    const float* __restrict__ A, const float* __restrict__ W,
    const float* __restrict__ bias, float* __restrict__ Cf,
    __half* __restrict__ Ch, int mode)
{
    const int K = 1024, N = 1024;
    __shared__ float As[2][BM * SPAD];
    __shared__ float Ws[2][BN * SPAD];

    int tid  = threadIdx.x;
    int bn   = blockIdx.x * BN;
    int bm   = blockIdx.y * BM;
    int warp = tid >> 5, lane = tid & 31;
    int r = lane >> 2, g = lane & 3;
    int wm = (warp >> 1) * 32;
    int wn = (warp & 1) * 64;

    float acc[2][8][4];
#pragma unroll
    for (int mi = 0; mi < 2; mi++)
#pragma unroll
        for (int ni = 0; ni < 8; ni++)
#pragma unroll
            for (int e = 0; e < 4; e++) acc[mi][ni][e] = 0.0f;

    {
#pragma unroll
        for (int u = 0; u < 2; u++) {
            int ch  = tid + u * 256;
            int row = ch >> 2;
            int kc  = (ch & 3) * 4;
            cp_async16(&As[0][row * SPAD + kc], &A[(size_t)(bm + row) * K + kc]);
            cp_async16(&Ws[0][row * SPAD + kc], &W[(size_t)(bn + row) * K + kc]);
        }
        CP_COMMIT;
    }

    int buf = 0;
    for (int k0 = 0; k0 < K; k0 += BKG) {
        CP_WAIT0;
        __syncthreads();

        if (k0 + BKG < K) {
            int nb = buf ^ 1;
            int kn = k0 + BKG;
#pragma unroll
            for (int u = 0; u < 2; u++) {
                int ch  = tid + u * 256;
                int row = ch >> 2;
                int kc  = (ch & 3) * 4;
                cp_async16(&As[nb][row * SPAD + kc], &A[(size_t)(bm + row) * K + kn + kc]);
                cp_async16(&Ws[nb][row * SPAD + kc], &W[(size_t)(bn + row) * K + kn + kc]);
            }
            CP_COMMIT;
        }

        const float* as = As[buf];
        const float* ws = Ws[buf];
#pragma unroll
        for (int kk = 0; kk < BKG; kk += 8) {
            uint32_t a[2][4];
#pragma unroll
            for (int mi = 0; mi < 2; mi++) {
                int base = (wm + mi * 16 + r) * SPAD + kk + g;
                a[mi][0] = __float_as_uint(as[base]);
                a[mi][1] = __float_as_uint(as[base + 8 * SPAD]);
                a[mi][2] = __float_as_uint(as[base + 4]);
                a[mi][3] = __float_as_uint(as[base + 8 * SPAD + 4]);
            }
            uint32_t b[8][2];
#pragma unroll
            for (int ni = 0; ni < 8; ni++) {
                int base = (wn + ni * 8 + r) * SPAD + kk + g;
                b[ni][0] = __float_as_uint(ws[base]);
                b[ni][1] = __float_as_uint(ws[base + 4]);
            }
#pragma unroll
            for (int mi = 0; mi < 2; mi++)
#pragma unroll
                for (int ni = 0; ni < 8; ni++)
                    mma_tf32(acc[mi][ni], a[mi][0], a[mi][1], a[mi][2], a[mi][3],
                             b[ni][0], b[ni][1]);
        }
        buf ^= 1;
    }

#pragma unroll
    for (int mi = 0; mi < 2; mi++) {
        int row0 = bm + wm + mi * 16 + r;
#pragma unroll
        for (int ni = 0; ni < 8; ni++) {
            int col = bn + wn + ni * 8 + 2 * g;
            float b0 = bias[col], b1 = bias[col + 1];
            float v0x = acc[mi][ni][0] + b0;
            float v0y = acc[mi][ni][1] + b1;
            float v1x = acc[mi][ni][2] + b0;
            float v1y = acc[mi][ni][3] + b1;
            if (mode == 1) {  // fp16 out for attention consumption
                ((uint32_t*)Ch)[((size_t)row0 * N + col) >> 1]       = pack_h2(v0x, v0y);
                ((uint32_t*)Ch)[((size_t)(row0 + 8) * N + col) >> 1] = pack_h2(v1x, v1y);
            } else {
                float2 w0, w1;
                w0.x = v0x; w0.y = v0y;
                w1.x = v1x; w1.y = v1y;
                *(float2*)&Cf[(size_t)row0 * N + col]       = w0;
                *(float2*)&Cf[(size_t)(row0 + 8) * N + col] = w1;
            }
        }
    }
}

// fused QKV projections: blockIdx.z selects {v,k,q}; fp16 outputs
__global__ void __launch_bounds__(256) gemm_qkv(
    const float* __restrict__ bv, const float* __restrict__ bk,
    const float* __restrict__ bq)
{
    int z = blockIdx.z;
    const float* A    = g_rin + (size_t)z * MR * DD;
    const float* W    = g_rw  + (size_t)z * DD * DD;
    const float* bias = (z == 0) ? bv : (z == 1) ? bk : bq;
    __half*      C    = (z == 0) ? g_vh : (z == 1) ? g_kh : g_qh;
    gemm_body(A, W, bias, (float*)0, C, 1);
}

// output projection (fp32 out)
__global__ void __launch_bounds__(256) gemm_out(
    const float* __restrict__ A, const float* __restrict__ bias,
    float* __restrict__ C)
{
    gemm_body(A, g_rw + 3 * (size_t)DD * DD, bias, C, (__half*)0, 0);
}

// ---------------- fp16 tensor-core flash attention ---------------------------
// grid (B*H, S/128), 256 threads = 8 warps; warp w owns q rows w*16..+15.
// K-tiles of 64 keys, K+V double-buffered (static smem 36.9KB), 1 sync/tile.
// m16n8k16 f16 MMA; V B-frags via ldmatrix.trans; P stays in registers
// (score C-frag layout == PV A-frag layout for f16: direct pack, no shfl).
#define AK   64
#define AQ   128
#define HST  72                  // halfs per smem row (144B: conflict-free)
#define HTILE (AK * HST)         // halfs per tile

__global__ void __launch_bounds__(256) attn_kernel()
{
    __shared__ __half sK[2][HTILE];
    __shared__ __half sV[2][HTILE];

    int tid  = threadIdx.x;
    int warp = tid >> 5, lane = tid & 31;
    int r = lane >> 2, g = lane & 3;
    int b  = blockIdx.x >> 4;
    int h  = blockIdx.x & 15;
    int q0 = blockIdx.y * AQ;
    int w16 = warp * 16;
    const int bSS = b * SS;

    // ---- Q A-fragments from gmem halves (L2-hot) ----
    uint32_t aq[4][4];
    {
        const __half* qp  = g_qh + (size_t)(bSS + q0 + w16 + r) * DD + h * DH;
        const __half* qp8 = qp + 8 * DD;
#pragma unroll
        for (int ks = 0; ks < 4; ks++) {
            int c = ks * 16 + 2 * g;
            aq[ks][0] = *(const uint32_t*)&qp[c];
            aq[ks][1] = *(const uint32_t*)&qp8[c];
            aq[ks][2] = *(const uint32_t*)&qp[c + 8];
            aq[ks][3] = *(const uint32_t*)&qp8[c + 8];
        }
    }

    // ---- prefetch tile 0 (K+V) ----
    for (int cch = tid; cch < AK * 8; cch += 256) {
        int row = cch >> 3;
        int c   = cch & 7;
        size_t go = (size_t)(bSS + row) * DD + h * DH + c * 8;
        cp_async16(&sK[0][row * HST + c * 8], &g_kh[go]);
        cp_async16(&sV[0][row * HST + c * 8], &g_vh[go]);
    }
    CP_COMMIT;

    uint32_t sk0 = (uint32_t)__cvta_generic_to_shared(&sK[0][0]);
    uint32_t sv0 = (uint32_t)__cvta_generic_to_shared(&sV[0][0]);
    const int TILE_B = HTILE * 2;  // bytes per tile buffer

    // lane-constant ldmatrix offsets (bytes)
    int t4 = lane >> 3, lr = lane & 7;
    uint32_t kOff = (uint32_t)(((t4 >> 1) * 8 + lr) * 144 + (t4 & 1) * 16);
    uint32_t vOff = (uint32_t)(((t4 & 1) * 8 + lr) * 144 + (t4 >> 1) * 16);

    float o[8][4];
#pragma unroll
    for (int nt = 0; nt < 8; nt++)
#pragma unroll
        for (int e = 0; e < 4; e++) o[nt][e] = 0.0f;
    float m0 = -INFINITY, m1 = -INFINITY, l0 = 0.0f, l1 = 0.0f;

    const int NT = SS / AK;  // 16
    int buf = 0;
    for (int t = 0; t < NT; t++) {
        CP_WAIT0;
        __syncthreads();   // tile t visible; all warps done with buf^1

        if (t + 1 < NT) {
            int nb = buf ^ 1;
            for (int cch = tid; cch < AK * 8; cch += 256) {
                int row = cch >> 3;
                int c   = cch & 7;
                size_t go = (size_t)(bSS + (t + 1) * AK + row) * DD + h * DH + c * 8;
                cp_async16(&sK[nb][row * HST + c * 8], &g_kh[go]);
                cp_async16(&sV[nb][row * HST + c * 8], &g_vh[go]);
            }
            CP_COMMIT;
        }

        uint32_t skb = sk0 + buf * TILE_B + kOff;
        uint32_t svb = sv0 + buf * TILE_B + vOff;

        // ---- scores S = Q K^T (f16 m16n8k16, K B-frags via ldmatrix) ----
        float s[8][4];
#pragma unroll
        for (int nt = 0; nt < 8; nt++)
#pragma unroll
            for (int e = 0; e < 4; e++) s[nt][e] = 0.0f;

#pragma unroll
        for (int j = 0; j < 4; j++) {
#pragma unroll
            for (int ks = 0; ks < 4; ks++) {
                uint32_t kb[4];
                ldsm4(kb, skb + j * 2304 + ks * 32);
                mma_f16(s[2 * j],     aq[ks][0], aq[ks][1], aq[ks][2], aq[ks][3], kb[0], kb[1]);
                mma_f16(s[2 * j + 1], aq[ks][0], aq[ks][1], aq[ks][2], aq[ks][3], kb[2], kb[3]);
            }
        }

        // ---- online softmax on fragments; P packed to half2 in-lane ----
        int k0 = t * AK;
        float mx0 = -INFINITY, mx1 = -INFINITY;
#pragma unroll
        for (int nt = 0; nt < 8; nt++) {
            int col = k0 + nt * 8 + 2 * g;
            float bv0 = g_bias[bSS + col];
            float bv1 = g_bias[bSS + col + 1];
            s[nt][0] = s[nt][0] * 0.125f + bv0;
            s[nt][1] = s[nt][1] * 0.125f + bv1;
            s[nt][2] = s[nt][2] * 0.125f + bv0;
            s[nt][3] = s[nt][3] * 0.125f + bv1;
            mx0 = fmaxf(mx0, fmaxf(s[nt][0], s[nt][1]));
            mx1 = fmaxf(mx1, fmaxf(s[nt][2], s[nt][3]));
        }
        mx0 = fmaxf(mx0, __shfl_xor_sync(0xffffffffu, mx0, 1));
        mx0 = fmaxf(mx0, __shfl_xor_sync(0xffffffffu, mx0, 2));
        mx1 = fmaxf(mx1, __shfl_xor_sync(0xffffffffu, mx1, 1));
        mx1 = fmaxf(mx1, __shfl_xor_sync(0xffffffffu, mx1, 2));

        float m0n = fmaxf(m0, mx0), m1n = fmaxf(m1, mx1);
        float c0 = __expf(m0 - m0n), c1 = __expf(m1 - m1n);
        m0 = m0n; m1 = m1n;

        uint32_t ph[8][2];
        float sum0 = 0.0f, sum1 = 0.0f;
#pragma unroll
        for (int nt = 0; nt < 8; nt++) {
            float p00 = __expf(s[nt][0] - m0);
            float p01 = __expf(s[nt][1] - m0);
            float p10 = __expf(s[nt][2] - m1);
            float p11 = __expf(s[nt][3] - m1);
            sum0 += p00 + p01;
            sum1 += p10 + p11;
            ph[nt][0] = pack_h2(p00, p01);  // rows r
            ph[nt][1] = pack_h2(p10, p11);  // rows r+8
        }
        sum0 += __shfl_xor_sync(0xffffffffu, sum0, 1);
        sum0 += __shfl_xor_sync(0xffffffffu, sum0, 2);
        sum1 += __shfl_xor_sync(0xffffffffu, sum1, 1);
        sum1 += __shfl_xor_sync(0xffffffffu, sum1, 2);
        l0 = l0 * c0 + sum0;
        l1 = l1 * c1 + sum1;

#pragma unroll
        for (int nt = 0; nt < 8; nt++) {
            o[nt][0] *= c0; o[nt][1] *= c0;
            o[nt][2] *= c1; o[nt][3] *= c1;
        }

        // ---- O += P V (V B-frags via ldmatrix.trans; P A-frags in regs) ----
#pragma unroll
        for (int ksk = 0; ksk < 4; ksk++) {
            uint32_t a0 = ph[2 * ksk][0];
            uint32_t a1 = ph[2 * ksk][1];
            uint32_t a2 = ph[2 * ksk + 1][0];
            uint32_t a3 = ph[2 * ksk + 1][1];
#pragma unroll
            for (int j = 0; j < 4; j++) {
                uint32_t vb[4];
                ldsm4t(vb, svb + ksk * 2304 + j * 32);
                mma_f16(o[2 * j],     a0, a1, a2, a3, vb[0], vb[1]);
                mma_f16(o[2 * j + 1], a0, a1, a2, a3, vb[2], vb[3]);
            }
        }
        buf ^= 1;
    }

    // ---- normalize + pre-round tf32 (final GEMM input) + write merged heads
    float inv0 = 1.0f / l0, inv1 = 1.0f / l1;
#pragma unroll
    for (int nt = 0; nt < 8; nt++) {
        int col = h * DH + nt * 8 + 2 * g;
        float2 w0, w1;
        w0.x = f2tff(o[nt][0] * inv0); w0.y = f2tff(o[nt][1] * inv0);
        w1.x = f2tff(o[nt][2] * inv1); w1.y = f2tff(o[nt][3] * inv1);
        *(float2*)&g_attn[(size_t)(bSS + q0 + w16 + r) * DD + col]     = w0;
        *(float2*)&g_attn[(size_t)(bSS + q0 + w16 + r + 8) * DD + col] = w1;
    }
}

// ---------------- launch -----------------------------------------------------
extern "C" void kernel_launch(void* const* d_in, const int* in_sizes, int n_in,
                              void* d_out, int out_size)
{
    const float* v  = (const float*)d_in[0];
    const float* k  = (const float*)d_in[1];
    const float* q  = (const float*)d_in[2];
    const unsigned char* mask   = (const unsigned char*)d_in[3];
    const unsigned char* semask = (const unsigned char*)d_in[4];
    const float* Wv = (const float*)d_in[5];
    const float* bv = (const float*)d_in[6];
    const float* Wk = (const float*)d_in[7];
    const float* bk = (const float*)d_in[8];
    const float* Wq = (const float*)d_in[9];
    const float* bq = (const float*)d_in[10];
    const float* Wm = (const float*)d_in[11];
    const float* bm = (const float*)d_in[12];
    float* out = (float*)d_out;

    float* pa;
    cudaGetSymbolAddress((void**)&pa, g_attn);

    mask_bias_kernel<<<1, 256>>>(mask, semask);

    round_all<<<(3 * F4BIG + 4 * F4W) / 256, 256>>>(
        (const float4*)v, (const float4*)k, (const float4*)q,
        (const float4*)Wv, (const float4*)Wk, (const float4*)Wq,
        (const float4*)Wm);

    dim3 gg(1024 / BN, MR / BM, 3);  // (8, 32, 3) fused QKV -> fp16
    gemm_qkv<<<gg, 256>>>(bv, bk, bq);

    attn_kernel<<<dim3(BB * HH, SS / AQ), 256>>>();

    gemm_out<<<dim3(1024 / BN, MR / BM), 256>>>(pa, bm, out);
}

// round 9
// speedup vs baseline: 5.1847x; 1.5248x over previous
#include <cuda_runtime.h>
#include <cuda_fp16.h>
#include <math.h>
#include <stdint.h>

// Problem constants
#define BB 4
#define SS 1024
#define DD 1024
#define HH 16
#define DH 64
#define MR (BB * SS)   // 4096 rows

// ---------------- scratch (static device globals; allocation-free) ----------
__device__ __half g_qh[MR * DD];
__device__ __half g_kh[MR * DD];
__device__ __half g_vh[MR * DD];
__device__ __half g_attn[MR * DD];
__device__ float  g_bias[BB * SS];
__device__ __half g_inh[3 * MR * DD];  // fp16 v,k,q
__device__ __half g_wh[4 * DD * DD];   // fp16 Wv,Wk,Wq,Wm

// ---------------- small PTX helpers -----------------------------------------
__device__ __forceinline__ uint32_t pack_h2(float lo, float hi) {
    uint32_t d;
    asm("cvt.rn.f16x2.f32 %0, %1, %2;" : "=r"(d) : "f"(hi), "f"(lo));
    return d;
}

__device__ __forceinline__ void mma_f16(float c[4],
                                        uint32_t a0, uint32_t a1, uint32_t a2, uint32_t a3,
                                        uint32_t b0, uint32_t b1) {
    asm volatile(
        "mma.sync.aligned.m16n8k16.row.col.f32.f16.f16.f32 "
        "{%0,%1,%2,%3}, {%4,%5,%6,%7}, {%8,%9}, {%0,%1,%2,%3};"
        : "+f"(c[0]), "+f"(c[1]), "+f"(c[2]), "+f"(c[3])
        : "r"(a0), "r"(a1), "r"(a2), "r"(a3), "r"(b0), "r"(b1));
}

__device__ __forceinline__ void ldsm4(uint32_t r[4], uint32_t addr) {
    asm volatile("ldmatrix.sync.aligned.m8n8.x4.shared.b16 {%0,%1,%2,%3}, [%4];"
                 : "=r"(r[0]), "=r"(r[1]), "=r"(r[2]), "=r"(r[3]) : "r"(addr));
}
__device__ __forceinline__ void ldsm4t(uint32_t r[4], uint32_t addr) {
    asm volatile("ldmatrix.sync.aligned.m8n8.x4.trans.shared.b16 {%0,%1,%2,%3}, [%4];"
                 : "=r"(r[0]), "=r"(r[1]), "=r"(r[2]), "=r"(r[3]) : "r"(addr));
}

__device__ __forceinline__ void cp_async16(void* smem, const void* gmem) {
    uint32_t s = (uint32_t)__cvta_generic_to_shared(smem);
    asm volatile("cp.async.cg.shared.global [%0], [%1], 16;" :: "r"(s), "l"(gmem));
}
#define CP_COMMIT asm volatile("cp.async.commit_group;")
#define CP_WAIT0  asm volatile("cp.async.wait_group 0;")

// ---------------- mask -> additive bias, with dtype autodetect --------------
__global__ void __launch_bounds__(256) mask_bias_kernel(
    const unsigned char* __restrict__ m8, const unsigned char* __restrict__ s8)
{
    __shared__ int flag_off, flag_f32;
    if (threadIdx.x == 0) { flag_off = 0; flag_f32 = 0; }
    __syncthreads();

    int loc_off = 0, loc_f32 = 0;
    for (int p = threadIdx.x; p < BB * SS; p += blockDim.x) {
        unsigned char bm = m8[p];
        unsigned char bs = s8[p];
        if ((p & 3) != 0) {
            if (bm | bs) loc_off = 1;
            if (bm == 0x3f || bm == 0x80 || bs == 0x3f || bs == 0x80) loc_f32 = 1;
        }
    }
    if (loc_off) atomicOr(&flag_off, 1);
    if (loc_f32) atomicOr(&flag_f32, 1);
    __syncthreads();

    int code = flag_f32 ? 2 : (flag_off ? 0 : 1);  // 0=bool8, 1=int32, 2=f32

    for (int i = threadIdx.x; i < BB * SS; i += blockDim.x) {
        bool mv, sv;
        if (code == 0) {
            mv = m8[i] != 0;
            sv = s8[i] != 0;
        } else if (code == 1) {
            mv = ((const int*)m8)[i] != 0;
            sv = ((const int*)s8)[i] != 0;
        } else {
            mv = ((const float*)m8)[i] != 0.0f;
            sv = ((const float*)s8)[i] != 0.0f;
        }
        g_bias[i] = (mv || sv) ? -1e9f : 0.0f;
    }
}

// ---------------- pack v,k,q + weights to fp16 -------------------------------
#define H8BIG (MR * DD / 8)   // 524288 8-half chunks per big tensor
#define H8W   (DD * DD / 8)   // 131072 per weight

__global__ void __launch_bounds__(256) pack_f16(
    const float4* __restrict__ v, const float4* __restrict__ k,
    const float4* __restrict__ q,
    const float4* __restrict__ Wv, const float4* __restrict__ Wk,
    const float4* __restrict__ Wq, const float4* __restrict__ Wm)
{
    size_t t = (size_t)blockIdx.x * blockDim.x + threadIdx.x;
    const float4* src;
    __half* dst;
    if (t < H8BIG) {
        src = v + t * 2;                     dst = g_inh + t * 8;
    } else if (t < 2 * (size_t)H8BIG) {
        src = k + (t - H8BIG) * 2;           dst = g_inh + t * 8;
    } else if (t < 3 * (size_t)H8BIG) {
        src = q + (t - 2 * H8BIG) * 2;       dst = g_inh + t * 8;
    } else {
        size_t tw  = t - 3 * (size_t)H8BIG;
        int    seg = (int)(tw / H8W);
        size_t off = tw - (size_t)seg * H8W;
        const float4* ws[4] = { Wv, Wk, Wq, Wm };
        src = ws[seg] + off * 2;
        dst = g_wh + tw * 8;
    }
    float4 x = src[0], y = src[1];
    uint4 o;
    o.x = pack_h2(x.x, x.y);
    o.y = pack_h2(x.z, x.w);
    o.z = pack_h2(y.x, y.y);
    o.w = pack_h2(y.z, y.w);
    *(uint4*)dst = o;
}

// ---------------- fp16 tensor-core GEMM: C = A[M,K] * W[N,K]^T + bias[N] ----
// 128x128 tile, BK=32 halves double-buffered; 8 warps (4x2), warp tile 32x64.
// m16n8k16; A and B fragments via ldmatrix.
#define BKH  32
#define SROW 40   // smem halves per row (80B): i*80 mod 128B hits all 8 offsets
#define GT_HALF (128 * SROW)

// mode 0: fp32 out; mode 1: fp16 out
__device__ __forceinline__ void gemm_f16_body(
    const __half* __restrict__ A, const __half* __restrict__ W,
    const float* __restrict__ bias, float* __restrict__ Cf,
    __half* __restrict__ Ch, int mode)
{
    const int K = 1024, N = 1024;
    __shared__ __half As[2][GT_HALF];
    __shared__ __half Ws[2][GT_HALF];

    int tid  = threadIdx.x;
    int bn   = blockIdx.x * 128;
    int bm   = blockIdx.y * 128;
    int warp = tid >> 5, lane = tid & 31;
    int r = lane >> 2, g = lane & 3;
    int wm = (warp >> 1) * 32;
    int wn = (warp & 1) * 64;

    float acc[2][8][4];
#pragma unroll
    for (int mi = 0; mi < 2; mi++)
#pragma unroll
        for (int ni = 0; ni < 8; ni++)
#pragma unroll
            for (int e = 0; e < 4; e++) acc[mi][ni][e] = 0.0f;

    // lane-constant ldmatrix byte offsets
    int t4 = lane >> 3, lr = lane & 7;
    uint32_t aOff = (uint32_t)((lane & 15) * 80 + (lane >> 4) * 16);
    uint32_t wOff = (uint32_t)(((t4 >> 1) * 8 + lr) * 80 + (t4 & 1) * 16);

    uint32_t sa0 = (uint32_t)__cvta_generic_to_shared(&As[0][0]);
    uint32_t sw0 = (uint32_t)__cvta_generic_to_shared(&Ws[0][0]);
    const int TB = GT_HALF * 2;  // bytes per buffer

    // prologue: stage 0
#pragma unroll
    for (int u = 0; u < 2; u++) {
        int ch  = tid + u * 256;      // 0..511
        int row = ch >> 2;
        int c8  = (ch & 3) * 8;
        cp_async16(&As[0][row * SROW + c8], &A[(size_t)(bm + row) * K + c8]);
        cp_async16(&Ws[0][row * SROW + c8], &W[(size_t)(bn + row) * K + c8]);
    }
    CP_COMMIT;

    int buf = 0;
    for (int k0 = 0; k0 < K; k0 += BKH) {
        CP_WAIT0;
        __syncthreads();

        if (k0 + BKH < K) {
            int nb = buf ^ 1;
            int kn = k0 + BKH;
#pragma unroll
            for (int u = 0; u < 2; u++) {
                int ch  = tid + u * 256;
                int row = ch >> 2;
                int c8  = (ch & 3) * 8;
                cp_async16(&As[nb][row * SROW + c8], &A[(size_t)(bm + row) * K + kn + c8]);
                cp_async16(&Ws[nb][row * SROW + c8], &W[(size_t)(bn + row) * K + kn + c8]);
            }
            CP_COMMIT;
        }

        uint32_t sa = sa0 + buf * TB;
        uint32_t sw = sw0 + buf * TB + wn * 80 + wOff;
#pragma unroll
        for (int kk = 0; kk < 2; kk++) {   // two k16 slices
            uint32_t a[2][4];
            ldsm4(a[0], sa + (wm)      * 80 + kk * 32 + aOff);
            ldsm4(a[1], sa + (wm + 16) * 80 + kk * 32 + aOff);
#pragma unroll
            for (int j = 0; j < 4; j++) {
                uint32_t wb[4];
                ldsm4(wb, sw + j * 1280 + kk * 32);
                mma_f16(acc[0][2 * j],     a[0][0], a[0][1], a[0][2], a[0][3], wb[0], wb[1]);
                mma_f16(acc[0][2 * j + 1], a[0][0], a[0][1], a[0][2], a[0][3], wb[2], wb[3]);
                mma_f16(acc[1][2 * j],     a[1][0], a[1][1], a[1][2], a[1][3], wb[0], wb[1]);
                mma_f16(acc[1][2 * j + 1], a[1][0], a[1][1], a[1][2], a[1][3], wb[2], wb[3]);
            }
        }
        buf ^= 1;
    }

    // epilogue: bias + store
#pragma unroll
    for (int mi = 0; mi < 2; mi++) {
        int row0 = bm + wm + mi * 16 + r;
#pragma unroll
        for (int ni = 0; ni < 8; ni++) {
            int col = bn + wn + ni * 8 + 2 * g;
            float b0 = bias[col], b1 = bias[col + 1];
            float v0x = acc[mi][ni][0] + b0;
            float v0y = acc[mi][ni][1] + b1;
            float v1x = acc[mi][ni][2] + b0;
            float v1y = acc[mi][ni][3] + b1;
            if (mode == 1) {
                ((uint32_t*)Ch)[((size_t)row0 * N + col) >> 1]       = pack_h2(v0x, v0y);
                ((uint32_t*)Ch)[((size_t)(row0 + 8) * N + col) >> 1] = pack_h2(v1x, v1y);
            } else {
                float2 w0, w1;
                w0.x = v0x; w0.y = v0y;
                w1.x = v1x; w1.y = v1y;
                *(float2*)&Cf[(size_t)row0 * N + col]       = w0;
                *(float2*)&Cf[(size_t)(row0 + 8) * N + col] = w1;
            }
        }
    }
}

// fused QKV projections: blockIdx.z selects {v,k,q}; fp16 outputs
__global__ void __launch_bounds__(256) gemm_qkv(
    const float* __restrict__ bv, const float* __restrict__ bk,
    const float* __restrict__ bq)
{
    int z = blockIdx.z;
    const __half* A    = g_inh + (size_t)z * MR * DD;
    const __half* W    = g_wh  + (size_t)z * DD * DD;
    const float*  bias = (z == 0) ? bv : (z == 1) ? bk : bq;
    __half*       C    = (z == 0) ? g_vh : (z == 1) ? g_kh : g_qh;
    gemm_f16_body(A, W, bias, (float*)0, C, 1);
}

// output projection (fp32 out), A = attention output (fp16)
__global__ void __launch_bounds__(256) gemm_out(
    const float* __restrict__ bias, float* __restrict__ C)
{
    gemm_f16_body(g_attn, g_wh + 3 * (size_t)DD * DD, bias, C, (__half*)0, 0);
}

// ---------------- fp16 tensor-core flash attention ---------------------------
#define AK   64
#define AQ   128
#define HST  72
#define HTILE (AK * HST)

__global__ void __launch_bounds__(256) attn_kernel()
{
    __shared__ __half sK[2][HTILE];
    __shared__ __half sV[2][HTILE];

    int tid  = threadIdx.x;
    int warp = tid >> 5, lane = tid & 31;
    int r = lane >> 2, g = lane & 3;
    int b  = blockIdx.x >> 4;
    int h  = blockIdx.x & 15;
    int q0 = blockIdx.y * AQ;
    int w16 = warp * 16;
    const int bSS = b * SS;

    uint32_t aq[4][4];
    {
        const __half* qp  = g_qh + (size_t)(bSS + q0 + w16 + r) * DD + h * DH;
        const __half* qp8 = qp + 8 * DD;
#pragma unroll
        for (int ks = 0; ks < 4; ks++) {
            int c = ks * 16 + 2 * g;
            aq[ks][0] = *(const uint32_t*)&qp[c];
            aq[ks][1] = *(const uint32_t*)&qp8[c];
            aq[ks][2] = *(const uint32_t*)&qp[c + 8];
            aq[ks][3] = *(const uint32_t*)&qp8[c + 8];
        }
    }

    for (int cch = tid; cch < AK * 8; cch += 256) {
        int row = cch >> 3;
        int c   = cch & 7;
        size_t go = (size_t)(bSS + row) * DD + h * DH + c * 8;
        cp_async16(&sK[0][row * HST + c * 8], &g_kh[go]);
        cp_async16(&sV[0][row * HST + c * 8], &g_vh[go]);
    }
    CP_COMMIT;

    uint32_t sk0 = (uint32_t)__cvta_generic_to_shared(&sK[0][0]);
    uint32_t sv0 = (uint32_t)__cvta_generic_to_shared(&sV[0][0]);
    const int TILE_B = HTILE * 2;

    int t4 = lane >> 3, lr = lane & 7;
    uint32_t kOff = (uint32_t)(((t4 >> 1) * 8 + lr) * 144 + (t4 & 1) * 16);
    uint32_t vOff = (uint32_t)(((t4 & 1) * 8 + lr) * 144 + (t4 >> 1) * 16);

    float o[8][4];
#pragma unroll
    for (int nt = 0; nt < 8; nt++)
#pragma unroll
        for (int e = 0; e < 4; e++) o[nt][e] = 0.0f;
    float m0 = -INFINITY, m1 = -INFINITY, l0 = 0.0f, l1 = 0.0f;

    const int NT = SS / AK;  // 16
    int buf = 0;
    for (int t = 0; t < NT; t++) {
        CP_WAIT0;
        __syncthreads();

        if (t + 1 < NT) {
            int nb = buf ^ 1;
            for (int cch = tid; cch < AK * 8; cch += 256) {
                int row = cch >> 3;
                int c   = cch & 7;
                size_t go = (size_t)(bSS + (t + 1) * AK + row) * DD + h * DH + c * 8;
                cp_async16(&sK[nb][row * HST + c * 8], &g_kh[go]);
                cp_async16(&sV[nb][row * HST + c * 8], &g_vh[go]);
            }
            CP_COMMIT;
        }

        uint32_t skb = sk0 + buf * TILE_B + kOff;
        uint32_t svb = sv0 + buf * TILE_B + vOff;

        float s[8][4];
#pragma unroll
        for (int nt = 0; nt < 8; nt++)
#pragma unroll
            for (int e = 0; e < 4; e++) s[nt][e] = 0.0f;

#pragma unroll
        for (int j = 0; j < 4; j++) {
#pragma unroll
            for (int ks = 0; ks < 4; ks++) {
                uint32_t kb[4];
                ldsm4(kb, skb + j * 2304 + ks * 32);
                mma_f16(s[2 * j],     aq[ks][0], aq[ks][1], aq[ks][2], aq[ks][3], kb[0], kb[1]);
                mma_f16(s[2 * j + 1], aq[ks][0], aq[ks][1], aq[ks][2], aq[ks][3], kb[2], kb[3]);
            }
        }

        int k0 = t * AK;
        float mx0 = -INFINITY, mx1 = -INFINITY;
#pragma unroll
        for (int nt = 0; nt < 8; nt++) {
            int col = k0 + nt * 8 + 2 * g;
            float bv0 = g_bias[bSS + col];
            float bv1 = g_bias[bSS + col + 1];
            s[nt][0] = s[nt][0] * 0.125f + bv0;
            s[nt][1] = s[nt][1] * 0.125f + bv1;
            s[nt][2] = s[nt][2] * 0.125f + bv0;
            s[nt][3] = s[nt][3] * 0.125f + bv1;
            mx0 = fmaxf(mx0, fmaxf(s[nt][0], s[nt][1]));
            mx1 = fmaxf(mx1, fmaxf(s[nt][2], s[nt][3]));
        }
        mx0 = fmaxf(mx0, __shfl_xor_sync(0xffffffffu, mx0, 1));
        mx0 = fmaxf(mx0, __shfl_xor_sync(0xffffffffu, mx0, 2));
        mx1 = fmaxf(mx1, __shfl_xor_sync(0xffffffffu, mx1, 1));
        mx1 = fmaxf(mx1, __shfl_xor_sync(0xffffffffu, mx1, 2));

        float m0n = fmaxf(m0, mx0), m1n = fmaxf(m1, mx1);
        float c0 = __expf(m0 - m0n), c1 = __expf(m1 - m1n);
        m0 = m0n; m1 = m1n;

        uint32_t ph[8][2];
        float sum0 = 0.0f, sum1 = 0.0f;
#pragma unroll
        for (int nt = 0; nt < 8; nt++) {
            float p00 = __expf(s[nt][0] - m0);
            float p01 = __expf(s[nt][1] - m0);
            float p10 = __expf(s[nt][2] - m1);
            float p11 = __expf(s[nt][3] - m1);
            sum0 += p00 + p01;
            sum1 += p10 + p11;
            ph[nt][0] = pack_h2(p00, p01);
            ph[nt][1] = pack_h2(p10, p11);
        }
        sum0 += __shfl_xor_sync(0xffffffffu, sum0, 1);
        sum0 += __shfl_xor_sync(0xffffffffu, sum0, 2);
        sum1 += __shfl_xor_sync(0xffffffffu, sum1, 1);
        sum1 += __shfl_xor_sync(0xffffffffu, sum1, 2);
        l0 = l0 * c0 + sum0;
        l1 = l1 * c1 + sum1;

#pragma unroll
        for (int nt = 0; nt < 8; nt++) {
            o[nt][0] *= c0; o[nt][1] *= c0;
            o[nt][2] *= c1; o[nt][3] *= c1;
        }

#pragma unroll
        for (int ksk = 0; ksk < 4; ksk++) {
            uint32_t a0 = ph[2 * ksk][0];
            uint32_t a1 = ph[2 * ksk][1];
            uint32_t a2 = ph[2 * ksk + 1][0];
            uint32_t a3 = ph[2 * ksk + 1][1];
#pragma unroll
            for (int j = 0; j < 4; j++) {
                uint32_t vb[4];
                ldsm4t(vb, svb + ksk * 2304 + j * 32);
                mma_f16(o[2 * j],     a0, a1, a2, a3, vb[0], vb[1]);
                mma_f16(o[2 * j + 1], a0, a1, a2, a3, vb[2], vb[3]);
            }
        }
        buf ^= 1;
    }

    // normalize + write fp16 merged heads (consumed by fp16 gemm_out)
    float inv0 = 1.0f / l0, inv1 = 1.0f / l1;
#pragma unroll
    for (int nt = 0; nt < 8; nt++) {
        int col = h * DH + nt * 8 + 2 * g;
        size_t i0 = (size_t)(bSS + q0 + w16 + r) * DD + col;
        size_t i1 = (size_t)(bSS + q0 + w16 + r + 8) * DD + col;
        ((uint32_t*)g_attn)[i0 >> 1] = pack_h2(o[nt][0] * inv0, o[nt][1] * inv0);
        ((uint32_t*)g_attn)[i1 >> 1] = pack_h2(o[nt][2] * inv1, o[nt][3] * inv1);
    }
}

// ---------------- launch -----------------------------------------------------
extern "C" void kernel_launch(void* const* d_in, const int* in_sizes, int n_in,
                              void* d_out, int out_size)
{
    const float* v  = (const float*)d_in[0];
    const float* k  = (const float*)d_in[1];
    const float* q  = (const float*)d_in[2];
    const unsigned char* mask   = (const unsigned char*)d_in[3];
    const unsigned char* semask = (const unsigned char*)d_in[4];
    const float* Wv = (const float*)d_in[5];
    const float* bv = (const float*)d_in[6];
    const float* Wk = (const float*)d_in[7];
    const float* bk = (const float*)d_in[8];
    const float* Wq = (const float*)d_in[9];
    const float* bq = (const float*)d_in[10];
    const float* Wm = (const float*)d_in[11];
    const float* bm = (const float*)d_in[12];
    float* out = (float*)d_out;

    mask_bias_kernel<<<1, 256>>>(mask, semask);

    pack_f16<<<(3 * H8BIG + 4 * H8W) / 256, 256>>>(
        (const float4*)v, (const float4*)k, (const float4*)q,
        (const float4*)Wv, (const float4*)Wk, (const float4*)Wq,
        (const float4*)Wm);

    dim3 gg(1024 / 128, MR / 128, 3);  // (8, 32, 3) fused QKV -> fp16
    gemm_qkv<<<gg, 256>>>(bv, bk, bq);

    attn_kernel<<<dim3(BB * HH, SS / AQ), 256>>>();

    gemm_out<<<dim3(1024 / 128, MR / 128), 256>>>(bm, out);
}

// round 10
// speedup vs baseline: 5.9850x; 1.1544x over previous
#include <cuda_runtime.h>
#include <cuda_fp16.h>
#include <math.h>
#include <stdint.h>

// Problem constants
#define BB 4
#define SS 1024
#define DD 1024
#define HH 16
#define DH 64
#define MR (BB * SS)   // 4096 rows

// 0.125 * log2(e): folded into Wq/bq so scores arrive in log2 domain
#define QSCALE 0.18033688011112042f

// ---------------- scratch (static device globals; allocation-free) ----------
__device__ __half g_qh[MR * DD];
__device__ __half g_kh[MR * DD];
__device__ __half g_vh[MR * DD];
__device__ __half g_attn[MR * DD];
__device__ float  g_bias[BB * SS];
__device__ __half g_inh[3 * MR * DD];  // fp16 v,k,q
__device__ __half g_wh[4 * DD * DD];   // fp16 Wv,Wk,Wq(x QSCALE),Wm

// ---------------- small PTX helpers -----------------------------------------
__device__ __forceinline__ uint32_t pack_h2(float lo, float hi) {
    uint32_t d;
    asm("cvt.rn.f16x2.f32 %0, %1, %2;" : "=r"(d) : "f"(hi), "f"(lo));
    return d;
}

__device__ __forceinline__ uint32_t h2ex2(uint32_t x) {
    uint32_t d;
    asm("ex2.approx.f16x2 %0, %1;" : "=r"(d) : "r"(x));
    return d;
}

__device__ __forceinline__ void mma_f16(float c[4],
                                        uint32_t a0, uint32_t a1, uint32_t a2, uint32_t a3,
                                        uint32_t b0, uint32_t b1) {
    asm volatile(
        "mma.sync.aligned.m16n8k16.row.col.f32.f16.f16.f32 "
        "{%0,%1,%2,%3}, {%4,%5,%6,%7}, {%8,%9}, {%0,%1,%2,%3};"
        : "+f"(c[0]), "+f"(c[1]), "+f"(c[2]), "+f"(c[3])
        : "r"(a0), "r"(a1), "r"(a2), "r"(a3), "r"(b0), "r"(b1));
}

__device__ __forceinline__ void ldsm4(uint32_t r[4], uint32_t addr) {
    asm volatile("ldmatrix.sync.aligned.m8n8.x4.shared.b16 {%0,%1,%2,%3}, [%4];"
                 : "=r"(r[0]), "=r"(r[1]), "=r"(r[2]), "=r"(r[3]) : "r"(addr));
}
__device__ __forceinline__ void ldsm4t(uint32_t r[4], uint32_t addr) {
    asm volatile("ldmatrix.sync.aligned.m8n8.x4.trans.shared.b16 {%0,%1,%2,%3}, [%4];"
                 : "=r"(r[0]), "=r"(r[1]), "=r"(r[2]), "=r"(r[3]) : "r"(addr));
}

__device__ __forceinline__ void cp_async16(void* smem, const void* gmem) {
    uint32_t s = (uint32_t)__cvta_generic_to_shared(smem);
    asm volatile("cp.async.cg.shared.global [%0], [%1], 16;" :: "r"(s), "l"(gmem));
}
#define CP_COMMIT asm volatile("cp.async.commit_group;")
#define CP_WAIT0  asm volatile("cp.async.wait_group 0;")

// ---------------- mask -> additive bias, with dtype autodetect --------------
__global__ void __launch_bounds__(256) mask_bias_kernel(
    const unsigned char* __restrict__ m8, const unsigned char* __restrict__ s8)
{
    __shared__ int flag_off, flag_f32;
    if (threadIdx.x == 0) { flag_off = 0; flag_f32 = 0; }
    __syncthreads();

    int loc_off = 0, loc_f32 = 0;
    for (int p = threadIdx.x; p < BB * SS; p += blockDim.x) {
        unsigned char bm = m8[p];
        unsigned char bs = s8[p];
        if ((p & 3) != 0) {
            if (bm | bs) loc_off = 1;
            if (bm == 0x3f || bm == 0x80 || bs == 0x3f || bs == 0x80) loc_f32 = 1;
        }
    }
    if (loc_off) atomicOr(&flag_off, 1);
    if (loc_f32) atomicOr(&flag_f32, 1);
    __syncthreads();

    int code = flag_f32 ? 2 : (flag_off ? 0 : 1);  // 0=bool8, 1=int32, 2=f32

    for (int i = threadIdx.x; i < BB * SS; i += blockDim.x) {
        bool mv, sv;
        if (code == 0) {
            mv = m8[i] != 0;
            sv = s8[i] != 0;
        } else if (code == 1) {
            mv = ((const int*)m8)[i] != 0;
            sv = ((const int*)s8)[i] != 0;
        } else {
            mv = ((const float*)m8)[i] != 0.0f;
            sv = ((const float*)s8)[i] != 0.0f;
        }
        g_bias[i] = (mv || sv) ? -1e9f : 0.0f;  // -1e9 is -inf in log2 domain too
    }
}

// ---------------- pack v,k,q + weights to fp16 (Wq scaled by QSCALE) --------
#define H8BIG (MR * DD / 8)   // 524288 8-half chunks per big tensor
#define H8W   (DD * DD / 8)   // 131072 per weight

__global__ void __launch_bounds__(256) pack_f16(
    const float4* __restrict__ v, const float4* __restrict__ k,
    const float4* __restrict__ q,
    const float4* __restrict__ Wv, const float4* __restrict__ Wk,
    const float4* __restrict__ Wq, const float4* __restrict__ Wm)
{
    size_t t = (size_t)blockIdx.x * blockDim.x + threadIdx.x;
    const float4* src;
    __half* dst;
    float sc = 1.0f;
    if (t < H8BIG) {
        src = v + t * 2;                     dst = g_inh + t * 8;
    } else if (t < 2 * (size_t)H8BIG) {
        src = k + (t - H8BIG) * 2;           dst = g_inh + t * 8;
    } else if (t < 3 * (size_t)H8BIG) {
        src = q + (t - 2 * H8BIG) * 2;       dst = g_inh + t * 8;
    } else {
        size_t tw  = t - 3 * (size_t)H8BIG;
        int    seg = (int)(tw / H8W);
        size_t off = tw - (size_t)seg * H8W;
        const float4* ws[4] = { Wv, Wk, Wq, Wm };
        src = ws[seg] + off * 2;
        dst = g_wh + tw * 8;
        if (seg == 2) sc = QSCALE;
    }
    float4 x = src[0], y = src[1];
    uint4 o;
    o.x = pack_h2(x.x * sc, x.y * sc);
    o.y = pack_h2(x.z * sc, x.w * sc);
    o.z = pack_h2(y.x * sc, y.y * sc);
    o.w = pack_h2(y.z * sc, y.w * sc);
    *(uint4*)dst = o;
}

// ---------------- fp16 tensor-core GEMM: C = A[M,K] * W[N,K]^T + bias[N] ----
#define BKH  32
#define SROW 40   // smem halves per row (80B): i*80 mod 128B hits all 8 offsets
#define GT_HALF (128 * SROW)

// mode 0: fp32 out; mode 1: fp16 out. bias scaled by bscale.
__device__ __forceinline__ void gemm_f16_body(
    const __half* __restrict__ A, const __half* __restrict__ W,
    const float* __restrict__ bias, float bscale, float* __restrict__ Cf,
    __half* __restrict__ Ch, int mode)
{
    const int K = 1024, N = 1024;
    __shared__ __half As[2][GT_HALF];
    __shared__ __half Ws[2][GT_HALF];

    int tid  = threadIdx.x;
    int bn   = blockIdx.x * 128;
    int bm   = blockIdx.y * 128;
    int warp = tid >> 5, lane = tid & 31;
    int r = lane >> 2, g = lane & 3;
    int wm = (warp >> 1) * 32;
    int wn = (warp & 1) * 64;

    float acc[2][8][4];
#pragma unroll
    for (int mi = 0; mi < 2; mi++)
#pragma unroll
        for (int ni = 0; ni < 8; ni++)
#pragma unroll
            for (int e = 0; e < 4; e++) acc[mi][ni][e] = 0.0f;

    int t4 = lane >> 3, lr = lane & 7;
    uint32_t aOff = (uint32_t)((lane & 15) * 80 + (lane >> 4) * 16);
    uint32_t wOff = (uint32_t)(((t4 >> 1) * 8 + lr) * 80 + (t4 & 1) * 16);

    uint32_t sa0 = (uint32_t)__cvta_generic_to_shared(&As[0][0]);
    uint32_t sw0 = (uint32_t)__cvta_generic_to_shared(&Ws[0][0]);
    const int TB = GT_HALF * 2;

#pragma unroll
    for (int u = 0; u < 2; u++) {
        int ch  = tid + u * 256;
        int row = ch >> 2;
        int c8  = (ch & 3) * 8;
        cp_async16(&As[0][row * SROW + c8], &A[(size_t)(bm + row) * K + c8]);
        cp_async16(&Ws[0][row * SROW + c8], &W[(size_t)(bn + row) * K + c8]);
    }
    CP_COMMIT;

    int buf = 0;
    for (int k0 = 0; k0 < K; k0 += BKH) {
        CP_WAIT0;
        __syncthreads();

        if (k0 + BKH < K) {
            int nb = buf ^ 1;
            int kn = k0 + BKH;
#pragma unroll
            for (int u = 0; u < 2; u++) {
                int ch  = tid + u * 256;
                int row = ch >> 2;
                int c8  = (ch & 3) * 8;
                cp_async16(&As[nb][row * SROW + c8], &A[(size_t)(bm + row) * K + kn + c8]);
                cp_async16(&Ws[nb][row * SROW + c8], &W[(size_t)(bn + row) * K + kn + c8]);
            }
            CP_COMMIT;
        }

        uint32_t sa = sa0 + buf * TB;
        uint32_t sw = sw0 + buf * TB + wn * 80 + wOff;
#pragma unroll
        for (int kk = 0; kk < 2; kk++) {
            uint32_t a[2][4];
            ldsm4(a[0], sa + (wm)      * 80 + kk * 32 + aOff);
            ldsm4(a[1], sa + (wm + 16) * 80 + kk * 32 + aOff);
#pragma unroll
            for (int j = 0; j < 4; j++) {
                uint32_t wb[4];
                ldsm4(wb, sw + j * 1280 + kk * 32);
                mma_f16(acc[0][2 * j],     a[0][0], a[0][1], a[0][2], a[0][3], wb[0], wb[1]);
                mma_f16(acc[0][2 * j + 1], a[0][0], a[0][1], a[0][2], a[0][3], wb[2], wb[3]);
                mma_f16(acc[1][2 * j],     a[1][0], a[1][1], a[1][2], a[1][3], wb[0], wb[1]);
                mma_f16(acc[1][2 * j + 1], a[1][0], a[1][1], a[1][2], a[1][3], wb[2], wb[3]);
            }
        }
        buf ^= 1;
    }

#pragma unroll
    for (int mi = 0; mi < 2; mi++) {
        int row0 = bm + wm + mi * 16 + r;
#pragma unroll
        for (int ni = 0; ni < 8; ni++) {
            int col = bn + wn + ni * 8 + 2 * g;
            float b0 = bias[col] * bscale, b1 = bias[col + 1] * bscale;
            float v0x = acc[mi][ni][0] + b0;
            float v0y = acc[mi][ni][1] + b1;
            float v1x = acc[mi][ni][2] + b0;
            float v1y = acc[mi][ni][3] + b1;
            if (mode == 1) {
                ((uint32_t*)Ch)[((size_t)row0 * N + col) >> 1]       = pack_h2(v0x, v0y);
                ((uint32_t*)Ch)[((size_t)(row0 + 8) * N + col) >> 1] = pack_h2(v1x, v1y);
            } else {
                float2 w0, w1;
                w0.x = v0x; w0.y = v0y;
                w1.x = v1x; w1.y = v1y;
                *(float2*)&Cf[(size_t)row0 * N + col]       = w0;
                *(float2*)&Cf[(size_t)(row0 + 8) * N + col] = w1;
            }
        }
    }
}

// fused QKV projections: blockIdx.z selects {v,k,q}; fp16 outputs
__global__ void __launch_bounds__(256) gemm_qkv(
    const float* __restrict__ bv, const float* __restrict__ bk,
    const float* __restrict__ bq)
{
    int z = blockIdx.z;
    const __half* A    = g_inh + (size_t)z * MR * DD;
    const __half* W    = g_wh  + (size_t)z * DD * DD;
    const float*  bias = (z == 0) ? bv : (z == 1) ? bk : bq;
    __half*       C    = (z == 0) ? g_vh : (z == 1) ? g_kh : g_qh;
    float bs           = (z == 2) ? QSCALE : 1.0f;
    gemm_f16_body(A, W, bias, bs, (float*)0, C, 1);
}

// output projection (fp32 out), A = attention output (fp16)
__global__ void __launch_bounds__(256) gemm_out(
    const float* __restrict__ bias, float* __restrict__ C)
{
    gemm_f16_body(g_attn, g_wh + 3 * (size_t)DD * DD, bias, 1.0f, C, (__half*)0, 0);
}

// ---------------- fp16 tensor-core flash attention (log2-domain softmax) ----
// Scores arrive in log2 domain (QSCALE folded into Wq). p = ex2.f16x2.
// V tile rows widened to 88 halves with a ones-column at col 64: the PV MMA's
// 9th n-group accumulates exact fp32 row-sums (= l), corr-rescaled like O.
#define AK    64
#define AQ    128
#define HSTK  72                  // K row stride (144B, conflict-free)
#define HSTV  88                  // V row stride (176B, conflict-free, room for ones col)
#define KTILE (AK * HSTK)
#define VTILE (AK * HSTV)

__global__ void __launch_bounds__(256) attn_kernel()
{
    __shared__ __half sK[2][KTILE];
    __shared__ __half sV[2][VTILE];

    int tid  = threadIdx.x;
    int warp = tid >> 5, lane = tid & 31;
    int r = lane >> 2, g = lane & 3;
    int b  = blockIdx.x >> 4;
    int h  = blockIdx.x & 15;
    int q0 = blockIdx.y * AQ;
    int w16 = warp * 16;
    const int bSS = b * SS;

    // ones-column init: col 64 = 1.0, cols 65..87 = 0 (both buffers)
    if (tid < 128) {
        int bufi = tid >> 6, row = tid & 63;
        __half* p = &sV[bufi][row * HSTV + 64];
        p[0] = __ushort_as_half((unsigned short)0x3C00);
#pragma unroll
        for (int c = 1; c < 24; c++) p[c] = __ushort_as_half((unsigned short)0);
    }

    // Q A-fragments from gmem halves (L2-hot)
    uint32_t aq[4][4];
    {
        const __half* qp  = g_qh + (size_t)(bSS + q0 + w16 + r) * DD + h * DH;
        const __half* qp8 = qp + 8 * DD;
#pragma unroll
        for (int ks = 0; ks < 4; ks++) {
            int c = ks * 16 + 2 * g;
            aq[ks][0] = *(const uint32_t*)&qp[c];
            aq[ks][1] = *(const uint32_t*)&qp8[c];
            aq[ks][2] = *(const uint32_t*)&qp[c + 8];
            aq[ks][3] = *(const uint32_t*)&qp8[c + 8];
        }
    }

    for (int cch = tid; cch < AK * 8; cch += 256) {
        int row = cch >> 3;
        int c   = cch & 7;
        size_t go = (size_t)(bSS + row) * DD + h * DH + c * 8;
        cp_async16(&sK[0][row * HSTK + c * 8], &g_kh[go]);
        cp_async16(&sV[0][row * HSTV + c * 8], &g_vh[go]);
    }
    CP_COMMIT;

    uint32_t sk0 = (uint32_t)__cvta_generic_to_shared(&sK[0][0]);
    uint32_t sv0 = (uint32_t)__cvta_generic_to_shared(&sV[0][0]);
    const int TBK = KTILE * 2;
    const int TBV = VTILE * 2;

    int t4 = lane >> 3, lr = lane & 7;
    uint32_t kOff = (uint32_t)(((t4 >> 1) * 8 + lr) * 144 + (t4 & 1) * 16);
    uint32_t vOff = (uint32_t)(((t4 & 1) * 8 + lr) * 176 + (t4 >> 1) * 16);

    float o[9][4];   // o[8] = ones-column accumulator (l)
#pragma unroll
    for (int nt = 0; nt < 9; nt++)
#pragma unroll
        for (int e = 0; e < 4; e++) o[nt][e] = 0.0f;
    float m0 = -INFINITY, m1 = -INFINITY;

    const int NT = SS / AK;  // 16
    int buf = 0;
    for (int t = 0; t < NT; t++) {
        CP_WAIT0;
        __syncthreads();

        if (t + 1 < NT) {
            int nb = buf ^ 1;
            for (int cch = tid; cch < AK * 8; cch += 256) {
                int row = cch >> 3;
                int c   = cch & 7;
                size_t go = (size_t)(bSS + (t + 1) * AK + row) * DD + h * DH + c * 8;
                cp_async16(&sK[nb][row * HSTK + c * 8], &g_kh[go]);
                cp_async16(&sV[nb][row * HSTV + c * 8], &g_vh[go]);
            }
            CP_COMMIT;
        }

        uint32_t skb = sk0 + buf * TBK + kOff;
        uint32_t svb = sv0 + buf * TBV + vOff;

        // scores S = Q K^T (log2 domain)
        float s[8][4];
#pragma unroll
        for (int nt = 0; nt < 8; nt++)
#pragma unroll
            for (int e = 0; e < 4; e++) s[nt][e] = 0.0f;

#pragma unroll
        for (int j = 0; j < 4; j++) {
#pragma unroll
            for (int ks = 0; ks < 4; ks++) {
                uint32_t kb[4];
                ldsm4(kb, skb + j * 2304 + ks * 32);
                mma_f16(s[2 * j],     aq[ks][0], aq[ks][1], aq[ks][2], aq[ks][3], kb[0], kb[1]);
                mma_f16(s[2 * j + 1], aq[ks][0], aq[ks][1], aq[ks][2], aq[ks][3], kb[2], kb[3]);
            }
        }

        // online softmax (log2 domain): bias add + max
        int k0t = t * AK;
        float mx0 = -INFINITY, mx1 = -INFINITY;
#pragma unroll
        for (int nt = 0; nt < 8; nt++) {
            int col = k0t + nt * 8 + 2 * g;
            float bv0 = g_bias[bSS + col];
            float bv1 = g_bias[bSS + col + 1];
            s[nt][0] += bv0;
            s[nt][1] += bv1;
            s[nt][2] += bv0;
            s[nt][3] += bv1;
            mx0 = fmaxf(mx0, fmaxf(s[nt][0], s[nt][1]));
            mx1 = fmaxf(mx1, fmaxf(s[nt][2], s[nt][3]));
        }
        mx0 = fmaxf(mx0, __shfl_xor_sync(0xffffffffu, mx0, 1));
        mx0 = fmaxf(mx0, __shfl_xor_sync(0xffffffffu, mx0, 2));
        mx1 = fmaxf(mx1, __shfl_xor_sync(0xffffffffu, mx1, 1));
        mx1 = fmaxf(mx1, __shfl_xor_sync(0xffffffffu, mx1, 2));

        float m0n = fmaxf(m0, mx0), m1n = fmaxf(m1, mx1);
        float c0 = exp2f(m0 - m0n), c1 = exp2f(m1 - m1n);
        m0 = m0n; m1 = m1n;

        // p = 2^(s-m) via f16x2 ex2 (half the MUFU issues)
        uint32_t ph[8][2];
#pragma unroll
        for (int nt = 0; nt < 8; nt++) {
            ph[nt][0] = h2ex2(pack_h2(s[nt][0] - m0, s[nt][1] - m0));
            ph[nt][1] = h2ex2(pack_h2(s[nt][2] - m1, s[nt][3] - m1));
        }

#pragma unroll
        for (int nt = 0; nt < 9; nt++) {
            o[nt][0] *= c0; o[nt][1] *= c0;
            o[nt][2] *= c1; o[nt][3] *= c1;
        }

        // O += P V (j=4: ones column -> l accumulator in fp32)
#pragma unroll
        for (int ksk = 0; ksk < 4; ksk++) {
            uint32_t a0 = ph[2 * ksk][0];
            uint32_t a1 = ph[2 * ksk][1];
            uint32_t a2 = ph[2 * ksk + 1][0];
            uint32_t a3 = ph[2 * ksk + 1][1];
#pragma unroll
            for (int j = 0; j < 4; j++) {
                uint32_t vb[4];
                ldsm4t(vb, svb + ksk * 2816 + j * 32);
                mma_f16(o[2 * j],     a0, a1, a2, a3, vb[0], vb[1]);
                mma_f16(o[2 * j + 1], a0, a1, a2, a3, vb[2], vb[3]);
            }
            {
                uint32_t vb[4];
                ldsm4t(vb, svb + ksk * 2816 + 4 * 32);
                mma_f16(o[8], a0, a1, a2, a3, vb[0], vb[1]);
            }
        }
        buf ^= 1;
    }

    // l lives in lane g=0 of each quad (column 64); broadcast
    float l0 = __shfl_sync(0xffffffffu, o[8][0], lane & 28);
    float l1 = __shfl_sync(0xffffffffu, o[8][2], lane & 28);

    // normalize + write fp16 merged heads (consumed by fp16 gemm_out)
    float inv0 = 1.0f / l0, inv1 = 1.0f / l1;
#pragma unroll
    for (int nt = 0; nt < 8; nt++) {
        int col = h * DH + nt * 8 + 2 * g;
        size_t i0 = (size_t)(bSS + q0 + w16 + r) * DD + col;
        size_t i1 = (size_t)(bSS + q0 + w16 + r + 8) * DD + col;
        ((uint32_t*)g_attn)[i0 >> 1] = pack_h2(o[nt][0] * inv0, o[nt][1] * inv0);
        ((uint32_t*)g_attn)[i1 >> 1] = pack_h2(o[nt][2] * inv1, o[nt][3] * inv1);
    }
}

// ---------------- launch -----------------------------------------------------
extern "C" void kernel_launch(void* const* d_in, const int* in_sizes, int n_in,
                              void* d_out, int out_size)
{
    const float* v  = (const float*)d_in[0];
    const float* k  = (const float*)d_in[1];
    const float* q  = (const float*)d_in[2];
    const unsigned char* mask   = (const unsigned char*)d_in[3];
    const unsigned char* semask = (const unsigned char*)d_in[4];
    const float* Wv = (const float*)d_in[5];
    const float* bv = (const float*)d_in[6];
    const float* Wk = (const float*)d_in[7];
    const float* bk = (const float*)d_in[8];
    const float* Wq = (const float*)d_in[9];
    const float* bq = (const float*)d_in[10];
    const float* Wm = (const float*)d_in[11];
    const float* bm = (const float*)d_in[12];
    float* out = (float*)d_out;

    mask_bias_kernel<<<1, 256>>>(mask, semask);

    pack_f16<<<(3 * H8BIG + 4 * H8W) / 256, 256>>>(
        (const float4*)v, (const float4*)k, (const float4*)q,
        (const float4*)Wv, (const float4*)Wk, (const float4*)Wq,
        (const float4*)Wm);

    dim3 gg(1024 / 128, MR / 128, 3);  // (8, 32, 3) fused QKV -> fp16
    gemm_qkv<<<gg, 256>>>(bv, bk, bq);

    attn_kernel<<<dim3(BB * HH, SS / AQ), 256>>>();

    gemm_out<<<dim3(1024 / 128, MR / 128), 256>>>(bm, out);
}

// round 11
// speedup vs baseline: 6.0325x; 1.0079x over previous
#include <cuda_runtime.h>
#include <cuda_fp16.h>
#include <math.h>
#include <stdint.h>

// Problem constants
#define BB 4
#define SS 1024
#define DD 1024
#define HH 16
#define DH 64
#define MR (BB * SS)   // 4096 rows

// 0.125 * log2(e): folded into Wq/bq so scores arrive in log2 domain
#define QSCALE 0.18033688011112042f
#define NEGINF_H (-60000.0f)   // fp16-representable "-inf" for masked keys

// ---------------- scratch (static device globals; allocation-free) ----------
__device__ __half g_qh[MR * DD];
__device__ __half g_kh[MR * DD];
__device__ __half g_vh[MR * DD];
__device__ __half g_attn[MR * DD];
__device__ __half g_biash[BB * SS];
__device__ __half g_inh[3 * MR * DD];  // fp16 v,k,q
__device__ __half g_wh[4 * DD * DD];   // fp16 Wv,Wk,Wq(x QSCALE),Wm

// ---------------- small PTX helpers -----------------------------------------
__device__ __forceinline__ uint32_t pack_h2(float lo, float hi) {
    uint32_t d;
    asm("cvt.rn.f16x2.f32 %0, %1, %2;" : "=r"(d) : "f"(hi), "f"(lo));
    return d;
}

__device__ __forceinline__ uint32_t h2ex2(uint32_t x) {
    uint32_t d;
    asm("ex2.approx.f16x2 %0, %1;" : "=r"(d) : "r"(x));
    return d;
}

__device__ __forceinline__ void mma_f16(float c[4],
                                        uint32_t a0, uint32_t a1, uint32_t a2, uint32_t a3,
                                        uint32_t b0, uint32_t b1) {
    asm volatile(
        "mma.sync.aligned.m16n8k16.row.col.f32.f16.f16.f32 "
        "{%0,%1,%2,%3}, {%4,%5,%6,%7}, {%8,%9}, {%0,%1,%2,%3};"
        : "+f"(c[0]), "+f"(c[1]), "+f"(c[2]), "+f"(c[3])
        : "r"(a0), "r"(a1), "r"(a2), "r"(a3), "r"(b0), "r"(b1));
}

__device__ __forceinline__ void ldsm4(uint32_t r[4], uint32_t addr) {
    asm volatile("ldmatrix.sync.aligned.m8n8.x4.shared.b16 {%0,%1,%2,%3}, [%4];"
                 : "=r"(r[0]), "=r"(r[1]), "=r"(r[2]), "=r"(r[3]) : "r"(addr));
}
__device__ __forceinline__ void ldsm4t(uint32_t r[4], uint32_t addr) {
    asm volatile("ldmatrix.sync.aligned.m8n8.x4.trans.shared.b16 {%0,%1,%2,%3}, [%4];"
                 : "=r"(r[0]), "=r"(r[1]), "=r"(r[2]), "=r"(r[3]) : "r"(addr));
}

__device__ __forceinline__ void cp_async16(void* smem, const void* gmem) {
    uint32_t s = (uint32_t)__cvta_generic_to_shared(smem);
    asm volatile("cp.async.cg.shared.global [%0], [%1], 16;" :: "r"(s), "l"(gmem));
}
#define CP_COMMIT asm volatile("cp.async.commit_group;")
#define CP_WAIT0  asm volatile("cp.async.wait_group 0;")

// ---------------- mask -> fp16 additive bias, with dtype autodetect ---------
__global__ void __launch_bounds__(256) mask_bias_kernel(
    const unsigned char* __restrict__ m8, const unsigned char* __restrict__ s8)
{
    __shared__ int flag_off, flag_f32;
    if (threadIdx.x == 0) { flag_off = 0; flag_f32 = 0; }
    __syncthreads();

    int loc_off = 0, loc_f32 = 0;
    for (int p = threadIdx.x; p < BB * SS; p += blockDim.x) {
        unsigned char bm = m8[p];
        unsigned char bs = s8[p];
        if ((p & 3) != 0) {
            if (bm | bs) loc_off = 1;
            if (bm == 0x3f || bm == 0x80 || bs == 0x3f || bs == 0x80) loc_f32 = 1;
        }
    }
    if (loc_off) atomicOr(&flag_off, 1);
    if (loc_f32) atomicOr(&flag_f32, 1);
    __syncthreads();

    int code = flag_f32 ? 2 : (flag_off ? 0 : 1);  // 0=bool8, 1=int32, 2=f32

    for (int i = threadIdx.x; i < BB * SS; i += blockDim.x) {
        bool mv, sv;
        if (code == 0) {
            mv = m8[i] != 0;
            sv = s8[i] != 0;
        } else if (code == 1) {
            mv = ((const int*)m8)[i] != 0;
            sv = ((const int*)s8)[i] != 0;
        } else {
            mv = ((const float*)m8)[i] != 0.0f;
            sv = ((const float*)s8)[i] != 0.0f;
        }
        g_biash[i] = __float2half((mv || sv) ? NEGINF_H : 0.0f);
    }
}

// ---------------- pack v,k,q + weights to fp16 (Wq scaled by QSCALE) --------
#define H8BIG (MR * DD / 8)   // 524288 8-half chunks per big tensor
#define H8W   (DD * DD / 8)   // 131072 per weight

__global__ void __launch_bounds__(256) pack_f16(
    const float4* __restrict__ v, const float4* __restrict__ k,
    const float4* __restrict__ q,
    const float4* __restrict__ Wv, const float4* __restrict__ Wk,
    const float4* __restrict__ Wq, const float4* __restrict__ Wm)
{
    size_t t = (size_t)blockIdx.x * blockDim.x + threadIdx.x;
    const float4* src;
    __half* dst;
    float sc = 1.0f;
    if (t < H8BIG) {
        src = v + t * 2;                     dst = g_inh + t * 8;
    } else if (t < 2 * (size_t)H8BIG) {
        src = k + (t - H8BIG) * 2;           dst = g_inh + t * 8;
    } else if (t < 3 * (size_t)H8BIG) {
        src = q + (t - 2 * H8BIG) * 2;       dst = g_inh + t * 8;
    } else {
        size_t tw  = t - 3 * (size_t)H8BIG;
        int    seg = (int)(tw / H8W);
        size_t off = tw - (size_t)seg * H8W;
        const float4* ws[4] = { Wv, Wk, Wq, Wm };
        src = ws[seg] + off * 2;
        dst = g_wh + tw * 8;
        if (seg == 2) sc = QSCALE;
    }
    float4 x = src[0], y = src[1];
    uint4 o;
    o.x = pack_h2(x.x * sc, x.y * sc);
    o.y = pack_h2(x.z * sc, x.w * sc);
    o.z = pack_h2(y.x * sc, y.y * sc);
    o.w = pack_h2(y.z * sc, y.w * sc);
    *(uint4*)dst = o;
}

// ---------------- fp16 tensor-core GEMM: C = A[M,K] * W[N,K]^T + bias[N] ----
// 64x128 block tile, 128 threads (4 warps 2x2, warp tile 32x64), BK=32 halves
// double-buffered -> 4 CTAs/SM for latency hiding.
#define BKH  32
#define SROW 40   // smem halves per row (80B): i*80 mod 128B hits all 8 offsets
#define GA_HALF (64 * SROW)
#define GW_HALF (128 * SROW)

// mode 0: fp32 out; mode 1: fp16 out. bias scaled by bscale.
__device__ __forceinline__ void gemm_f16_body(
    const __half* __restrict__ A, const __half* __restrict__ W,
    const float* __restrict__ bias, float bscale, float* __restrict__ Cf,
    __half* __restrict__ Ch, int mode)
{
    const int K = 1024, N = 1024;
    __shared__ __half As[2][GA_HALF];
    __shared__ __half Ws[2][GW_HALF];

    int tid  = threadIdx.x;
    int bn   = blockIdx.x * 128;
    int bm   = blockIdx.y * 64;
    int warp = tid >> 5, lane = tid & 31;
    int r = lane >> 2, g = lane & 3;
    int wm = (warp >> 1) * 32;
    int wn = (warp & 1) * 64;

    float acc[2][8][4];
#pragma unroll
    for (int mi = 0; mi < 2; mi++)
#pragma unroll
        for (int ni = 0; ni < 8; ni++)
#pragma unroll
            for (int e = 0; e < 4; e++) acc[mi][ni][e] = 0.0f;

    int t4 = lane >> 3, lr = lane & 7;
    uint32_t aOff = (uint32_t)((lane & 15) * 80 + (lane >> 4) * 16);
    uint32_t wOff = (uint32_t)(((t4 >> 1) * 8 + lr) * 80 + (t4 & 1) * 16);

    uint32_t sa0 = (uint32_t)__cvta_generic_to_shared(&As[0][0]);
    uint32_t sw0 = (uint32_t)__cvta_generic_to_shared(&Ws[0][0]);
    const int TBA = GA_HALF * 2;
    const int TBW = GW_HALF * 2;

    // prologue: stage 0 (A: 256 chunks, W: 512 chunks; 128 threads)
#pragma unroll
    for (int u = 0; u < 2; u++) {
        int ch  = tid + u * 128;
        int row = ch >> 2;
        int c8  = (ch & 3) * 8;
        cp_async16(&As[0][row * SROW + c8], &A[(size_t)(bm + row) * K + c8]);
    }
#pragma unroll
    for (int u = 0; u < 4; u++) {
        int ch  = tid + u * 128;
        int row = ch >> 2;
        int c8  = (ch & 3) * 8;
        cp_async16(&Ws[0][row * SROW + c8], &W[(size_t)(bn + row) * K + c8]);
    }
    CP_COMMIT;

    int buf = 0;
    for (int k0 = 0; k0 < K; k0 += BKH) {
        CP_WAIT0;
        __syncthreads();

        if (k0 + BKH < K) {
            int nb = buf ^ 1;
            int kn = k0 + BKH;
#pragma unroll
            for (int u = 0; u < 2; u++) {
                int ch  = tid + u * 128;
                int row = ch >> 2;
                int c8  = (ch & 3) * 8;
                cp_async16(&As[nb][row * SROW + c8], &A[(size_t)(bm + row) * K + kn + c8]);
            }
#pragma unroll
            for (int u = 0; u < 4; u++) {
                int ch  = tid + u * 128;
                int row = ch >> 2;
                int c8  = (ch & 3) * 8;
                cp_async16(&Ws[nb][row * SROW + c8], &W[(size_t)(bn + row) * K + kn + c8]);
            }
            CP_COMMIT;
        }

        uint32_t sa = sa0 + buf * TBA;
        uint32_t sw = sw0 + buf * TBW + wn * 80 + wOff;
#pragma unroll
        for (int kk = 0; kk < 2; kk++) {
            uint32_t a[2][4];
            ldsm4(a[0], sa + (wm)      * 80 + kk * 32 + aOff);
            ldsm4(a[1], sa + (wm + 16) * 80 + kk * 32 + aOff);
#pragma unroll
            for (int j = 0; j < 4; j++) {
                uint32_t wb[4];
                ldsm4(wb, sw + j * 1280 + kk * 32);
                mma_f16(acc[0][2 * j],     a[0][0], a[0][1], a[0][2], a[0][3], wb[0], wb[1]);
                mma_f16(acc[0][2 * j + 1], a[0][0], a[0][1], a[0][2], a[0][3], wb[2], wb[3]);
                mma_f16(acc[1][2 * j],     a[1][0], a[1][1], a[1][2], a[1][3], wb[0], wb[1]);
                mma_f16(acc[1][2 * j + 1], a[1][0], a[1][1], a[1][2], a[1][3], wb[2], wb[3]);
            }
        }
        buf ^= 1;
    }

#pragma unroll
    for (int mi = 0; mi < 2; mi++) {
        int row0 = bm + wm + mi * 16 + r;
#pragma unroll
        for (int ni = 0; ni < 8; ni++) {
            int col = bn + wn + ni * 8 + 2 * g;
            float b0 = bias[col] * bscale, b1 = bias[col + 1] * bscale;
            float v0x = acc[mi][ni][0] + b0;
            float v0y = acc[mi][ni][1] + b1;
            float v1x = acc[mi][ni][2] + b0;
            float v1y = acc[mi][ni][3] + b1;
            if (mode == 1) {
                ((uint32_t*)Ch)[((size_t)row0 * N + col) >> 1]       = pack_h2(v0x, v0y);
                ((uint32_t*)Ch)[((size_t)(row0 + 8) * N + col) >> 1] = pack_h2(v1x, v1y);
            } else {
                float2 w0, w1;
                w0.x = v0x; w0.y = v0y;
                w1.x = v1x; w1.y = v1y;
                *(float2*)&Cf[(size_t)row0 * N + col]       = w0;
                *(float2*)&Cf[(size_t)(row0 + 8) * N + col] = w1;
            }
        }
    }
}

// fused QKV projections: blockIdx.z selects {v,k,q}; fp16 outputs
__global__ void __launch_bounds__(128) gemm_qkv(
    const float* __restrict__ bv, const float* __restrict__ bk,
    const float* __restrict__ bq)
{
    int z = blockIdx.z;
    const __half* A    = g_inh + (size_t)z * MR * DD;
    const __half* W    = g_wh  + (size_t)z * DD * DD;
    const float*  bias = (z == 0) ? bv : (z == 1) ? bk : bq;
    __half*       C    = (z == 0) ? g_vh : (z == 1) ? g_kh : g_qh;
    float bs           = (z == 2) ? QSCALE : 1.0f;
    gemm_f16_body(A, W, bias, bs, (float*)0, C, 1);
}

// output projection (fp32 out), A = attention output (fp16)
__global__ void __launch_bounds__(128) gemm_out(
    const float* __restrict__ bias, float* __restrict__ C)
{
    gemm_f16_body(g_attn, g_wh + 3 * (size_t)DD * DD, bias, 1.0f, C, (__half*)0, 0);
}

// ---------------- fp16 tensor-core flash attention (log2-domain softmax) ----
// Bias folded into score MMA: K rows widened to 88 halves with the fp16 mask
// bias at col 64 (cols 65-79 zero); Q supplies a constant ones-fragment for
// k-group 4. Removes the per-tile bias LDG + FADDs from the softmax chain.
// V keeps the ones-column at col 64 (row-sum -> l in the PV accumulator).
#define AK    64
#define AQ    128
#define HSTK  88                  // 176B rows, conflict-free
#define HSTV  88
#define KTILE (AK * HSTK)
#define VTILE (AK * HSTV)

__global__ void __launch_bounds__(256) attn_kernel()
{
    __shared__ __half sK[2][KTILE];
    __shared__ __half sV[2][VTILE];

    int tid  = threadIdx.x;
    int warp = tid >> 5, lane = tid & 31;
    int r = lane >> 2, g = lane & 3;
    int b  = blockIdx.x >> 4;
    int h  = blockIdx.x & 15;
    int q0 = blockIdx.y * AQ;
    int w16 = warp * 16;
    const int bSS = b * SS;

    // init: V ones-column (col 64=1, 65-87=0) and K pad zeros (cols 65-79);
    // K col 64 is overwritten per tile with the bias value.
    if (tid < 128) {
        int bufi = tid >> 6, row = tid & 63;
        __half* pv = &sV[bufi][row * HSTV + 64];
        pv[0] = __ushort_as_half((unsigned short)0x3C00);
#pragma unroll
        for (int c = 1; c < 24; c++) pv[c] = __ushort_as_half((unsigned short)0);
        __half* pk = &sK[bufi][row * HSTK + 65];
#pragma unroll
        for (int c = 0; c < 15; c++) pk[c] = __ushort_as_half((unsigned short)0);
    }

    // Q A-fragments from gmem halves (L2-hot)
    uint32_t aq[4][4];
    {
        const __half* qp  = g_qh + (size_t)(bSS + q0 + w16 + r) * DD + h * DH;
        const __half* qp8 = qp + 8 * DD;
#pragma unroll
        for (int ks = 0; ks < 4; ks++) {
            int c = ks * 16 + 2 * g;
            aq[ks][0] = *(const uint32_t*)&qp[c];
            aq[ks][1] = *(const uint32_t*)&qp8[c];
            aq[ks][2] = *(const uint32_t*)&qp[c + 8];
            aq[ks][3] = *(const uint32_t*)&qp8[c + 8];
        }
    }
    // constant ones-fragment for k-group 4 (Q'[*][64]=1, cols 65-79 = 0)
    const uint32_t aq4_01 = (g == 0) ? 0x00003C00u : 0u;

    // prefetch tile 0 (K+V) + bias column
    for (int cch = tid; cch < AK * 8; cch += 256) {
        int row = cch >> 3;
        int c   = cch & 7;
        size_t go = (size_t)(bSS + row) * DD + h * DH + c * 8;
        cp_async16(&sK[0][row * HSTK + c * 8], &g_kh[go]);
        cp_async16(&sV[0][row * HSTV + c * 8], &g_vh[go]);
    }
    if (tid < 64) sK[0][tid * HSTK + 64] = g_biash[bSS + tid];
    CP_COMMIT;

    uint32_t sk0 = (uint32_t)__cvta_generic_to_shared(&sK[0][0]);
    uint32_t sv0 = (uint32_t)__cvta_generic_to_shared(&sV[0][0]);
    const int TBK = KTILE * 2;
    const int TBV = VTILE * 2;

    int t4 = lane >> 3, lr = lane & 7;
    uint32_t kOff = (uint32_t)(((t4 >> 1) * 8 + lr) * 176 + (t4 & 1) * 16);
    uint32_t vOff = (uint32_t)(((t4 & 1) * 8 + lr) * 176 + (t4 >> 1) * 16);

    float o[9][4];   // o[8] = ones-column accumulator (l)
#pragma unroll
    for (int nt = 0; nt < 9; nt++)
#pragma unroll
        for (int e = 0; e < 4; e++) o[nt][e] = 0.0f;
    float m0 = -INFINITY, m1 = -INFINITY;

    const int NT = SS / AK;  // 16
    int buf = 0;
    for (int t = 0; t < NT; t++) {
        CP_WAIT0;
        __syncthreads();

        if (t + 1 < NT) {
            int nb = buf ^ 1;
            int k1 = (t + 1) * AK;
            for (int cch = tid; cch < AK * 8; cch += 256) {
                int row = cch >> 3;
                int c   = cch & 7;
                size_t go = (size_t)(bSS + k1 + row) * DD + h * DH + c * 8;
                cp_async16(&sK[nb][row * HSTK + c * 8], &g_kh[go]);
                cp_async16(&sV[nb][row * HSTV + c * 8], &g_vh[go]);
            }
            if (tid < 64) sK[nb][tid * HSTK + 64] = g_biash[bSS + k1 + tid];
            CP_COMMIT;
        }

        uint32_t skb = sk0 + buf * TBK + kOff;
        uint32_t svb = sv0 + buf * TBV + vOff;

        // scores S = Q' K'^T (log2 domain, bias included via k-group 4)
        float s[8][4];
#pragma unroll
        for (int nt = 0; nt < 8; nt++)
#pragma unroll
            for (int e = 0; e < 4; e++) s[nt][e] = 0.0f;

#pragma unroll
        for (int j = 0; j < 4; j++) {
#pragma unroll
            for (int ks = 0; ks < 4; ks++) {
                uint32_t kb[4];
                ldsm4(kb, skb + j * 2816 + ks * 32);
                mma_f16(s[2 * j],     aq[ks][0], aq[ks][1], aq[ks][2], aq[ks][3], kb[0], kb[1]);
                mma_f16(s[2 * j + 1], aq[ks][0], aq[ks][1], aq[ks][2], aq[ks][3], kb[2], kb[3]);
            }
            {   // bias group: A = ones-col frag, B = K' cols 64-79
                uint32_t kb[4];
                ldsm4(kb, skb + j * 2816 + 128);
                mma_f16(s[2 * j],     aq4_01, aq4_01, 0u, 0u, kb[0], kb[1]);
                mma_f16(s[2 * j + 1], aq4_01, aq4_01, 0u, 0u, kb[2], kb[3]);
            }
        }

        // online softmax (log2 domain)
        float mx0 = -INFINITY, mx1 = -INFINITY;
#pragma unroll
        for (int nt = 0; nt < 8; nt++) {
            mx0 = fmaxf(mx0, fmaxf(s[nt][0], s[nt][1]));
            mx1 = fmaxf(mx1, fmaxf(s[nt][2], s[nt][3]));
        }
        mx0 = fmaxf(mx0, __shfl_xor_sync(0xffffffffu, mx0, 1));
        mx0 = fmaxf(mx0, __shfl_xor_sync(0xffffffffu, mx0, 2));
        mx1 = fmaxf(mx1, __shfl_xor_sync(0xffffffffu, mx1, 1));
        mx1 = fmaxf(mx1, __shfl_xor_sync(0xffffffffu, mx1, 2));

        float m0n = fmaxf(m0, mx0), m1n = fmaxf(m1, mx1);
        float c0 = exp2f(m0 - m0n), c1 = exp2f(m1 - m1n);
        m0 = m0n; m1 = m1n;

        // p = 2^(s-m) via f16x2 ex2
        uint32_t ph[8][2];
#pragma unroll
        for (int nt = 0; nt < 8; nt++) {
            ph[nt][0] = h2ex2(pack_h2(s[nt][0] - m0, s[nt][1] - m0));
            ph[nt][1] = h2ex2(pack_h2(s[nt][2] - m1, s[nt][3] - m1));
        }

#pragma unroll
        for (int nt = 0; nt < 9; nt++) {
            o[nt][0] *= c0; o[nt][1] *= c0;
            o[nt][2] *= c1; o[nt][3] *= c1;
        }

        // O += P V (j=4: ones column -> l accumulator in fp32)
#pragma unroll
        for (int ksk = 0; ksk < 4; ksk++) {
            uint32_t a0 = ph[2 * ksk][0];
            uint32_t a1 = ph[2 * ksk][1];
            uint32_t a2 = ph[2 * ksk + 1][0];
            uint32_t a3 = ph[2 * ksk + 1][1];
#pragma unroll
            for (int j = 0; j < 4; j++) {
                uint32_t vb[4];
                ldsm4t(vb, svb + ksk * 2816 + j * 32);
                mma_f16(o[2 * j],     a0, a1, a2, a3, vb[0], vb[1]);
                mma_f16(o[2 * j + 1], a0, a1, a2, a3, vb[2], vb[3]);
            }
            {
                uint32_t vb[4];
                ldsm4t(vb, svb + ksk * 2816 + 4 * 32);
                mma_f16(o[8], a0, a1, a2, a3, vb[0], vb[1]);
            }
        }
        buf ^= 1;
    }

    // l lives in lane g=0 of each quad (column 64); broadcast
    float l0 = __shfl_sync(0xffffffffu, o[8][0], lane & 28);
    float l1 = __shfl_sync(0xffffffffu, o[8][2], lane & 28);

    // normalize + write fp16 merged heads (consumed by fp16 gemm_out)
    float inv0 = 1.0f / l0, inv1 = 1.0f / l1;
#pragma unroll
    for (int nt = 0; nt < 8; nt++) {
        int col = h * DH + nt * 8 + 2 * g;
        size_t i0 = (size_t)(bSS + q0 + w16 + r) * DD + col;
        size_t i1 = (size_t)(bSS + q0 + w16 + r + 8) * DD + col;
        ((uint32_t*)g_attn)[i0 >> 1] = pack_h2(o[nt][0] * inv0, o[nt][1] * inv0);
        ((uint32_t*)g_attn)[i1 >> 1] = pack_h2(o[nt][2] * inv1, o[nt][3] * inv1);
    }
}

// ---------------- launch -----------------------------------------------------
extern "C" void kernel_launch(void* const* d_in, const int* in_sizes, int n_in,
                              void* d_out, int out_size)
{
    const float* v  = (const float*)d_in[0];
    const float* k  = (const float*)d_in[1];
    const float* q  = (const float*)d_in[2];
    const unsigned char* mask   = (const unsigned char*)d_in[3];
    const unsigned char* semask = (const unsigned char*)d_in[4];
    const float* Wv = (const float*)d_in[5];
    const float* bv = (const float*)d_in[6];
    const float* Wk = (const float*)d_in[7];
    const float* bk = (const float*)d_in[8];
    const float* Wq = (const float*)d_in[9];
    const float* bq = (const float*)d_in[10];
    const float* Wm = (const float*)d_in[11];
    const float* bm = (const float*)d_in[12];
    float* out = (float*)d_out;

    mask_bias_kernel<<<1, 256>>>(mask, semask);

    pack_f16<<<(3 * H8BIG + 4 * H8W) / 256, 256>>>(
        (const float4*)v, (const float4*)k, (const float4*)q,
        (const float4*)Wv, (const float4*)Wk, (const float4*)Wq,
        (const float4*)Wm);

    dim3 gg(1024 / 128, MR / 64, 3);  // (8, 64, 3) fused QKV -> fp16
    gemm_qkv<<<gg, 128>>>(bv, bk, bq);

    attn_kernel<<<dim3(BB * HH, SS / AQ), 256>>>();

    gemm_out<<<dim3(1024 / 128, MR / 64), 128>>>(bm, out);
}